// round 1
// baseline (speedup 1.0000x reference)
#include <cuda_runtime.h>
#include <math.h>

#define N_NODES 200000
#define N_EDGES 3200000
#define G_GRAPHS 8192
#define HID 256
#define H2 128
#define CCOLS 512
#define EPS 1e-5f

// ---------------- scratch (device globals; no runtime alloc) ----------------
__device__ float g_bufA[(size_t)N_NODES * HID];
__device__ float g_bufB[(size_t)N_NODES * HID];
__device__ float g_dinv[N_NODES];
__device__ float g_cnt[G_GRAPHS];
__device__ float g_c[(size_t)G_GRAPHS * CCOLS];
__device__ float g_t1[(size_t)G_GRAPHS * HID];
__device__ float g_t2[(size_t)G_GRAPHS * H2];
__device__ float g_mu[HID];
__device__ float g_istd[HID];

// ---------------- utility kernels ----------------
__global__ void fill_kernel(float* __restrict__ p, float v, size_t n) {
    size_t i = (size_t)blockIdx.x * blockDim.x + threadIdx.x;
    if (i < n) p[i] = v;
}

__global__ void deg_accum_kernel(const int* __restrict__ cols, float* __restrict__ deg, int nE) {
    int i = blockIdx.x * blockDim.x + threadIdx.x;
    if (i < nE) atomicAdd(&deg[cols[i]], 1.0f);
}

__global__ void rsqrt_kernel(float* __restrict__ d, int n) {
    int i = blockIdx.x * blockDim.x + threadIdx.x;
    if (i < n) d[i] = rsqrtf(d[i]);
}

// out[i,:] = in[i,:] * dinv[i]^2   (self-loop term, also serves as the zero-init)
template <int D>
__global__ void self_init_kernel(const float* __restrict__ in, float* __restrict__ out,
                                 const float* __restrict__ dinv, int n) {
    size_t idx = (size_t)blockIdx.x * blockDim.x + threadIdx.x;
    if (idx >= (size_t)n * D) return;
    int i = (int)(idx / D);
    float w = dinv[i];
    out[idx] = in[idx] * w * w;
}

// one warp per edge: out[col,:] += in[row,:] * dinv[row]*dinv[col]
template <int D>
__global__ void agg_kernel(const float* __restrict__ in, float* __restrict__ out,
                           const int* __restrict__ rows, const int* __restrict__ cols,
                           const float* __restrict__ dinv, int nE) {
    int e = blockIdx.x * (blockDim.x >> 5) + (threadIdx.x >> 5);
    if (e >= nE) return;
    int lane = threadIdx.x & 31;
    int r = rows[e], c = cols[e];
    float w = dinv[r] * dinv[c];
    const float4* src = (const float4*)(in + (size_t)r * D);
    float* dst = out + (size_t)c * D;
#pragma unroll
    for (int v = 0; v < D / 128; v++) {
        float4 x = src[lane + v * 32];
        int base = (lane + v * 32) * 4;
        atomicAdd(&dst[base + 0], x.x * w);
        atomicAdd(&dst[base + 1], x.y * w);
        atomicAdd(&dst[base + 2], x.z * w);
        atomicAdd(&dst[base + 3], x.w * w);
    }
}

__global__ void count_kernel(const int* __restrict__ batch, float* __restrict__ cnt, int n) {
    int i = blockIdx.x * blockDim.x + threadIdx.x;
    if (i < n) atomicAdd(&cnt[batch[i]], 1.0f);
}

// c[batch[i], coff+d] += relu(buf[i,d] + bias[d])
__global__ void pool_kernel(const float* __restrict__ buf, const int* __restrict__ batch,
                            const float* __restrict__ bias, float* __restrict__ c,
                            int coff, int n) {
    size_t idx = (size_t)blockIdx.x * blockDim.x + threadIdx.x;
    if (idx >= (size_t)n * H2) return;
    int i = (int)(idx >> 7);
    int d = (int)(idx & 127);
    float v = buf[idx] + bias[d];
    v = fmaxf(v, 0.0f);
    atomicAdd(&c[(size_t)batch[i] * CCOLS + coff + d], v);
}

__global__ void pool_div_kernel(float* __restrict__ c, const float* __restrict__ cnt, int coff) {
    int idx = blockIdx.x * blockDim.x + threadIdx.x;
    if (idx >= G_GRAPHS * H2) return;
    int g = idx >> 7, d = idx & 127;
    c[(size_t)g * CCOLS + coff + d] *= 1.0f / fmaxf(cnt[g], 1.0f);
}

// ---------------- SGEMM: C[M,Nc] = (relu)(A[M,K] @ W[K,Nc] (+ bias)) ----------------
// BM=BN=64, BK=16, 256 threads, 4x4 per thread. M%64==0, Nc%64==0, K%16==0 guaranteed.
template <bool RELU, bool BIAS>
__global__ __launch_bounds__(256) void gemm_kernel(
    const float* __restrict__ A, const float* __restrict__ W,
    const float* __restrict__ bias, float* __restrict__ C,
    int M, int K, int Nc, int ldc, int coff) {
    __shared__ float As[16][68];
    __shared__ float Bs[16][68];
    int tid = threadIdx.x;
    int tx = tid & 15, ty = tid >> 4;
    int bm = blockIdx.y * 64, bn = blockIdx.x * 64;

    int arow = tid >> 2;            // 0..63
    int acol4 = (tid & 3) << 2;     // 0,4,8,12
    int brow = tid >> 4;            // 0..15
    int bcol4 = (tid & 15) << 2;    // 0..60

    float acc[4][4] = {};

    for (int k0 = 0; k0 < K; k0 += 16) {
        float4 a4 = *(const float4*)&A[(size_t)(bm + arow) * K + k0 + acol4];
        As[acol4 + 0][arow] = a4.x;
        As[acol4 + 1][arow] = a4.y;
        As[acol4 + 2][arow] = a4.z;
        As[acol4 + 3][arow] = a4.w;
        float4 b4 = *(const float4*)&W[(size_t)(k0 + brow) * Nc + bn + bcol4];
        *(float4*)&Bs[brow][bcol4] = b4;
        __syncthreads();
#pragma unroll
        for (int k = 0; k < 16; k++) {
            float4 av = *(const float4*)&As[k][ty << 2];
            float4 bv = *(const float4*)&Bs[k][tx << 2];
            float am[4] = {av.x, av.y, av.z, av.w};
            float bm_[4] = {bv.x, bv.y, bv.z, bv.w};
#pragma unroll
            for (int i = 0; i < 4; i++)
#pragma unroll
                for (int j = 0; j < 4; j++) acc[i][j] += am[i] * bm_[j];
        }
        __syncthreads();
    }

#pragma unroll
    for (int i = 0; i < 4; i++) {
        float* crow = C + (size_t)(bm + (ty << 2) + i) * ldc + coff + bn + (tx << 2);
#pragma unroll
        for (int j = 0; j < 4; j++) {
            float v = acc[i][j];
            if (BIAS) v += bias[bn + (tx << 2) + j];
            if (RELU) v = fmaxf(v, 0.0f);
            crow[j] = v;
        }
    }
}

// ---------------- batch norm ----------------
__global__ void bn_stats_kernel(const float* __restrict__ X, int C,
                                float* __restrict__ mu, float* __restrict__ istd) {
    int c = blockIdx.x;
    int tid = threadIdx.x;
    float s = 0.f, s2 = 0.f;
    for (int r = tid; r < G_GRAPHS; r += 256) {
        float v = X[(size_t)r * C + c];
        s += v;
        s2 += v * v;
    }
    __shared__ float sh[256], sh2[256];
    sh[tid] = s;
    sh2[tid] = s2;
    __syncthreads();
    for (int o = 128; o > 0; o >>= 1) {
        if (tid < o) {
            sh[tid] += sh[tid + o];
            sh2[tid] += sh2[tid + o];
        }
        __syncthreads();
    }
    if (tid == 0) {
        float m = sh[0] / (float)G_GRAPHS;
        float var = sh2[0] / (float)G_GRAPHS - m * m;
        mu[c] = m;
        istd[c] = rsqrtf(var + EPS);
    }
}

__global__ void bn_apply_kernel(float* __restrict__ X, const float* __restrict__ mu,
                                const float* __restrict__ istd, const float* __restrict__ gamma,
                                const float* __restrict__ beta, int C, int total) {
    int idx = blockIdx.x * blockDim.x + threadIdx.x;
    if (idx >= total) return;
    int c = idx % C;
    X[idx] = (X[idx] - mu[c]) * istd[c] * gamma[c] + beta[c];
}

// ---------------- host launcher ----------------
static inline int ceil_div(long long a, int b) { return (int)((a + b - 1) / b); }

extern "C" void kernel_launch(void* const* d_in, const int* in_sizes, int n_in,
                              void* d_out, int out_size) {
    const float* x[2] = {(const float*)d_in[0], (const float*)d_in[1]};
    const int* ei[2] = {(const int*)d_in[2], (const int*)d_in[3]};
    const int* batch[2] = {(const int*)d_in[4], (const int*)d_in[5]};
    const float* notes[2] = {(const float*)d_in[6], (const float*)d_in[7]};
    const float* Wc1 = (const float*)d_in[8];  const float* bc1 = (const float*)d_in[9];
    const float* Wc2 = (const float*)d_in[10]; const float* bc2 = (const float*)d_in[11];
    const float* Wc3 = (const float*)d_in[12]; const float* bc3 = (const float*)d_in[13];
    const float* Wc4 = (const float*)d_in[14]; const float* bc4 = (const float*)d_in[15];
    const float* Wn1 = (const float*)d_in[16]; const float* bn1b = (const float*)d_in[17];
    const float* Wn2 = (const float*)d_in[18]; const float* bn2b = (const float*)d_in[19];
    const float* Wf1 = (const float*)d_in[20]; const float* bf1 = (const float*)d_in[21];
    const float* g1 = (const float*)d_in[22];  const float* be1 = (const float*)d_in[23];
    const float* Wf2 = (const float*)d_in[24]; const float* bf2 = (const float*)d_in[25];
    const float* g2 = (const float*)d_in[26];  const float* be2 = (const float*)d_in[27];
    const float* Wf3 = (const float*)d_in[28]; const float* bf3 = (const float*)d_in[29];

    float *bufA, *bufB, *dinv, *cnt, *cbuf, *t1, *t2, *mu, *istd;
    cudaGetSymbolAddress((void**)&bufA, g_bufA);
    cudaGetSymbolAddress((void**)&bufB, g_bufB);
    cudaGetSymbolAddress((void**)&dinv, g_dinv);
    cudaGetSymbolAddress((void**)&cnt, g_cnt);
    cudaGetSymbolAddress((void**)&cbuf, g_c);
    cudaGetSymbolAddress((void**)&t1, g_t1);
    cudaGetSymbolAddress((void**)&t2, g_t2);
    cudaGetSymbolAddress((void**)&mu, g_mu);
    cudaGetSymbolAddress((void**)&istd, g_istd);

    const int TB = 256;
    const int N = N_NODES, E = N_EDGES, G = G_GRAPHS;

    // zero concat buffer (pooling accumulates into it)
    fill_kernel<<<ceil_div((long long)G * CCOLS, TB), TB>>>(cbuf, 0.0f, (size_t)G * CCOLS);

    for (int t = 0; t < 2; t++) {
        const int* rows = ei[t];
        const int* cols = ei[t] + E;

        // degree (init 1.0 for self loop) -> dinv
        fill_kernel<<<ceil_div(N, TB), TB>>>(dinv, 1.0f, (size_t)N);
        deg_accum_kernel<<<ceil_div(E, TB), TB>>>(cols, dinv, E);
        rsqrt_kernel<<<ceil_div(N, TB), TB>>>(dinv, N);

        // ---- layer 1: aggregate x at 128 dims, then GEMM+bias+relu -> bufB[N,256]
        self_init_kernel<128><<<ceil_div((long long)N * 128, TB), TB>>>(x[t], bufA, dinv, N);
        agg_kernel<128><<<ceil_div(E, 8), TB>>>(x[t], bufA, rows, cols, dinv, E);
        gemm_kernel<true, true><<<dim3(256 / 64, N / 64), 256>>>(bufA, Wc1, bc1, bufB, N, 128, 256, 256, 0);

        // ---- layer 2
        self_init_kernel<256><<<ceil_div((long long)N * 256, TB), TB>>>(bufB, bufA, dinv, N);
        agg_kernel<256><<<ceil_div(E, 8), TB>>>(bufB, bufA, rows, cols, dinv, E);
        gemm_kernel<true, true><<<dim3(256 / 64, N / 64), 256>>>(bufA, Wc2, bc2, bufB, N, 256, 256, 256, 0);

        // ---- layer 3
        self_init_kernel<256><<<ceil_div((long long)N * 256, TB), TB>>>(bufB, bufA, dinv, N);
        agg_kernel<256><<<ceil_div(E, 8), TB>>>(bufB, bufA, rows, cols, dinv, E);
        gemm_kernel<true, true><<<dim3(256 / 64, N / 64), 256>>>(bufA, Wc3, bc3, bufB, N, 256, 256, 256, 0);

        // ---- layer 4: GEMM first (no bias/relu), aggregate at 128 dims
        gemm_kernel<false, false><<<dim3(128 / 64, N / 64), 256>>>(bufB, Wc4, (const float*)0, bufA, N, 256, 128, 128, 0);
        self_init_kernel<128><<<ceil_div((long long)N * 128, TB), TB>>>(bufA, bufB, dinv, N);
        agg_kernel<128><<<ceil_div(E, 8), TB>>>(bufA, bufB, rows, cols, dinv, E);

        // ---- mean pool (bias+relu fused) into c[:, t*128 : t*128+128]
        fill_kernel<<<ceil_div(G, TB), TB>>>(cnt, 0.0f, (size_t)G);
        count_kernel<<<ceil_div(N, TB), TB>>>(batch[t], cnt, N);
        pool_kernel<<<ceil_div((long long)N * H2, TB), TB>>>(bufB, batch[t], bc4, cbuf, t * H2, N);
        pool_div_kernel<<<ceil_div(G * H2, TB), TB>>>(cbuf, cnt, t * H2);

        // ---- notes MLP into c[:, 256 + t*128 : ...]
        gemm_kernel<true, true><<<dim3(256 / 64, G / 64), 256>>>(notes[t], Wn1, bn1b, t1, G, 128, 256, 256, 0);
        gemm_kernel<true, true><<<dim3(128 / 64, G / 64), 256>>>(t1, Wn2, bn2b, cbuf, G, 256, 128, CCOLS, 256 + t * H2);
    }

    // ---- head: f1 = BN(relu(c @ Wf1 + bf1))
    gemm_kernel<true, true><<<dim3(256 / 64, G / 64), 256>>>(cbuf, Wf1, bf1, t1, G, 512, 256, 256, 0);
    bn_stats_kernel<<<256, 256>>>(t1, 256, mu, istd);
    bn_apply_kernel<<<ceil_div((long long)G * 256, TB), TB>>>(t1, mu, istd, g1, be1, 256, G * 256);

    // f2 = BN(relu(f1 @ Wf2 + bf2))
    gemm_kernel<true, true><<<dim3(128 / 64, G / 64), 256>>>(t1, Wf2, bf2, t2, G, 256, 128, 128, 0);
    bn_stats_kernel<<<128, 256>>>(t2, 128, mu, istd);
    bn_apply_kernel<<<ceil_div((long long)G * 128, TB), TB>>>(t2, mu, istd, g2, be2, 128, G * 128);

    // out = f2 @ Wf3 + bf3
    gemm_kernel<false, true><<<dim3(128 / 64, G / 64), 256>>>(t2, Wf3, bf3, (float*)d_out, G, 128, 128, 128, 0);
}

// round 2
// speedup vs baseline: 1.5798x; 1.5798x over previous
#include <cuda_runtime.h>
#include <math.h>

#define N_NODES 200000
#define N_EDGES 3200000
#define G_GRAPHS 8192
#define HID 256
#define H2 128
#define CCOLS 512
#define EPS 1e-5f

// ---------------- scratch (device globals; no runtime alloc) ----------------
__device__ float g_bufA[(size_t)N_NODES * HID];
__device__ float g_bufB[(size_t)N_NODES * HID];
__device__ float g_dinv[N_NODES];
__device__ float g_cnt[G_GRAPHS];
__device__ float g_c[(size_t)G_GRAPHS * CCOLS];
__device__ float g_t1[(size_t)G_GRAPHS * HID];
__device__ float g_t2[(size_t)G_GRAPHS * H2];
__device__ float g_mu[HID];
__device__ float g_istd[HID];

// vectorized fp32 reduction to global memory (sm_90+)
__device__ __forceinline__ void red_add_v4(float* addr, float4 v) {
    asm volatile("red.global.add.v4.f32 [%0], {%1, %2, %3, %4};"
                 :: "l"(addr), "f"(v.x), "f"(v.y), "f"(v.z), "f"(v.w)
                 : "memory");
}

// ---------------- utility kernels ----------------
__global__ void fill_kernel(float* __restrict__ p, float v, size_t n) {
    size_t i = (size_t)blockIdx.x * blockDim.x + threadIdx.x;
    if (i < n) p[i] = v;
}

__global__ void deg_accum_kernel(const int* __restrict__ cols, float* __restrict__ deg, int nE) {
    int i = blockIdx.x * blockDim.x + threadIdx.x;
    if (i < nE) atomicAdd(&deg[cols[i]], 1.0f);
}

__global__ void rsqrt_kernel(float* __restrict__ d, int n) {
    int i = blockIdx.x * blockDim.x + threadIdx.x;
    if (i < n) d[i] = rsqrtf(d[i]);
}

// out[i,:] = in[i,:] * dinv[i]^2   (self-loop term, also serves as the zero-init)
template <int D>
__global__ void self_init_kernel(const float* __restrict__ in, float* __restrict__ out,
                                 const float* __restrict__ dinv, int n) {
    size_t idx = (size_t)blockIdx.x * blockDim.x + threadIdx.x;
    if (idx >= (size_t)n * (D / 4)) return;
    int i = (int)(idx / (D / 4));
    float w = dinv[i];
    w = w * w;
    float4 v = ((const float4*)in)[idx];
    v.x *= w; v.y *= w; v.z *= w; v.w *= w;
    ((float4*)out)[idx] = v;
}

// one warp per edge: out[col,:] += in[row,:] * dinv[row]*dinv[col]
// scatter uses vectorized red.global.add.v4.f32 (1 L2 RED op per 16 bytes)
template <int D>
__global__ void agg_kernel(const float* __restrict__ in, float* __restrict__ out,
                           const int* __restrict__ rows, const int* __restrict__ cols,
                           const float* __restrict__ dinv, int nE) {
    int e = blockIdx.x * (blockDim.x >> 5) + (threadIdx.x >> 5);
    if (e >= nE) return;
    int lane = threadIdx.x & 31;
    int r = rows[e], c = cols[e];
    float w = dinv[r] * dinv[c];
    const float4* src = (const float4*)(in + (size_t)r * D);
    float4* dst = (float4*)(out + (size_t)c * D);
#pragma unroll
    for (int v = 0; v < D / 128; v++) {
        float4 x = src[lane + v * 32];
        x.x *= w; x.y *= w; x.z *= w; x.w *= w;
        red_add_v4((float*)&dst[lane + v * 32], x);
    }
}

__global__ void count_kernel(const int* __restrict__ batch, float* __restrict__ cnt, int n) {
    int i = blockIdx.x * blockDim.x + threadIdx.x;
    if (i < n) atomicAdd(&cnt[batch[i]], 1.0f);
}

// c[batch[i], coff+d..d+3] += relu(buf[i,d..d+3] + bias[d..d+3])  (vectorized)
__global__ void pool_kernel(const float* __restrict__ buf, const int* __restrict__ batch,
                            const float* __restrict__ bias, float* __restrict__ c,
                            int coff, int n) {
    size_t idx = (size_t)blockIdx.x * blockDim.x + threadIdx.x;  // over n * 32
    if (idx >= (size_t)n * 32) return;
    int i = (int)(idx >> 5);
    int d4 = (int)(idx & 31) * 4;
    float4 v = *(const float4*)&buf[(size_t)i * H2 + d4];
    float4 b = *(const float4*)&bias[d4];
    v.x = fmaxf(v.x + b.x, 0.0f);
    v.y = fmaxf(v.y + b.y, 0.0f);
    v.z = fmaxf(v.z + b.z, 0.0f);
    v.w = fmaxf(v.w + b.w, 0.0f);
    red_add_v4(&c[(size_t)batch[i] * CCOLS + coff + d4], v);
}

__global__ void pool_div_kernel(float* __restrict__ c, const float* __restrict__ cnt, int coff) {
    int idx = blockIdx.x * blockDim.x + threadIdx.x;
    if (idx >= G_GRAPHS * H2) return;
    int g = idx >> 7, d = idx & 127;
    c[(size_t)g * CCOLS + coff + d] *= 1.0f / fmaxf(cnt[g], 1.0f);
}

// ---------------- SGEMM: C[M,Nc] = (relu)(A[M,K] @ W[K,Nc] (+ bias)) ----------------
// BM=BN=64, BK=16, 256 threads, 4x4 per thread. M%64==0, Nc%64==0, K%16==0 guaranteed.
template <bool RELU, bool BIAS>
__global__ __launch_bounds__(256) void gemm_kernel(
    const float* __restrict__ A, const float* __restrict__ W,
    const float* __restrict__ bias, float* __restrict__ C,
    int M, int K, int Nc, int ldc, int coff) {
    __shared__ float As[16][68];
    __shared__ float Bs[16][68];
    int tid = threadIdx.x;
    int tx = tid & 15, ty = tid >> 4;
    int bm = blockIdx.y * 64, bn = blockIdx.x * 64;

    int arow = tid >> 2;            // 0..63
    int acol4 = (tid & 3) << 2;     // 0,4,8,12
    int brow = tid >> 4;            // 0..15
    int bcol4 = (tid & 15) << 2;    // 0..60

    float acc[4][4] = {};

    for (int k0 = 0; k0 < K; k0 += 16) {
        float4 a4 = *(const float4*)&A[(size_t)(bm + arow) * K + k0 + acol4];
        As[acol4 + 0][arow] = a4.x;
        As[acol4 + 1][arow] = a4.y;
        As[acol4 + 2][arow] = a4.z;
        As[acol4 + 3][arow] = a4.w;
        float4 b4 = *(const float4*)&W[(size_t)(k0 + brow) * Nc + bn + bcol4];
        *(float4*)&Bs[brow][bcol4] = b4;
        __syncthreads();
#pragma unroll
        for (int k = 0; k < 16; k++) {
            float4 av = *(const float4*)&As[k][ty << 2];
            float4 bv = *(const float4*)&Bs[k][tx << 2];
            float am[4] = {av.x, av.y, av.z, av.w};
            float bm_[4] = {bv.x, bv.y, bv.z, bv.w};
#pragma unroll
            for (int i = 0; i < 4; i++)
#pragma unroll
                for (int j = 0; j < 4; j++) acc[i][j] += am[i] * bm_[j];
        }
        __syncthreads();
    }

#pragma unroll
    for (int i = 0; i < 4; i++) {
        float* crow = C + (size_t)(bm + (ty << 2) + i) * ldc + coff + bn + (tx << 2);
#pragma unroll
        for (int j = 0; j < 4; j++) {
            float v = acc[i][j];
            if (BIAS) v += bias[bn + (tx << 2) + j];
            if (RELU) v = fmaxf(v, 0.0f);
            crow[j] = v;
        }
    }
}

// ---------------- batch norm ----------------
__global__ void bn_stats_kernel(const float* __restrict__ X, int C,
                                float* __restrict__ mu, float* __restrict__ istd) {
    int c = blockIdx.x;
    int tid = threadIdx.x;
    float s = 0.f, s2 = 0.f;
    for (int r = tid; r < G_GRAPHS; r += 256) {
        float v = X[(size_t)r * C + c];
        s += v;
        s2 += v * v;
    }
    __shared__ float sh[256], sh2[256];
    sh[tid] = s;
    sh2[tid] = s2;
    __syncthreads();
    for (int o = 128; o > 0; o >>= 1) {
        if (tid < o) {
            sh[tid] += sh[tid + o];
            sh2[tid] += sh2[tid + o];
        }
        __syncthreads();
    }
    if (tid == 0) {
        float m = sh[0] / (float)G_GRAPHS;
        float var = sh2[0] / (float)G_GRAPHS - m * m;
        mu[c] = m;
        istd[c] = rsqrtf(var + EPS);
    }
}

__global__ void bn_apply_kernel(float* __restrict__ X, const float* __restrict__ mu,
                                const float* __restrict__ istd, const float* __restrict__ gamma,
                                const float* __restrict__ beta, int C, int total) {
    int idx = blockIdx.x * blockDim.x + threadIdx.x;
    if (idx >= total) return;
    int c = idx % C;
    X[idx] = (X[idx] - mu[c]) * istd[c] * gamma[c] + beta[c];
}

// ---------------- host launcher ----------------
static inline int ceil_div(long long a, int b) { return (int)((a + b - 1) / b); }

extern "C" void kernel_launch(void* const* d_in, const int* in_sizes, int n_in,
                              void* d_out, int out_size) {
    const float* x[2] = {(const float*)d_in[0], (const float*)d_in[1]};
    const int* ei[2] = {(const int*)d_in[2], (const int*)d_in[3]};
    const int* batch[2] = {(const int*)d_in[4], (const int*)d_in[5]};
    const float* notes[2] = {(const float*)d_in[6], (const float*)d_in[7]};
    const float* Wc1 = (const float*)d_in[8];  const float* bc1 = (const float*)d_in[9];
    const float* Wc2 = (const float*)d_in[10]; const float* bc2 = (const float*)d_in[11];
    const float* Wc3 = (const float*)d_in[12]; const float* bc3 = (const float*)d_in[13];
    const float* Wc4 = (const float*)d_in[14]; const float* bc4 = (const float*)d_in[15];
    const float* Wn1 = (const float*)d_in[16]; const float* bn1b = (const float*)d_in[17];
    const float* Wn2 = (const float*)d_in[18]; const float* bn2b = (const float*)d_in[19];
    const float* Wf1 = (const float*)d_in[20]; const float* bf1 = (const float*)d_in[21];
    const float* g1 = (const float*)d_in[22];  const float* be1 = (const float*)d_in[23];
    const float* Wf2 = (const float*)d_in[24]; const float* bf2 = (const float*)d_in[25];
    const float* g2 = (const float*)d_in[26];  const float* be2 = (const float*)d_in[27];
    const float* Wf3 = (const float*)d_in[28]; const float* bf3 = (const float*)d_in[29];

    float *bufA, *bufB, *dinv, *cnt, *cbuf, *t1, *t2, *mu, *istd;
    cudaGetSymbolAddress((void**)&bufA, g_bufA);
    cudaGetSymbolAddress((void**)&bufB, g_bufB);
    cudaGetSymbolAddress((void**)&dinv, g_dinv);
    cudaGetSymbolAddress((void**)&cnt, g_cnt);
    cudaGetSymbolAddress((void**)&cbuf, g_c);
    cudaGetSymbolAddress((void**)&t1, g_t1);
    cudaGetSymbolAddress((void**)&t2, g_t2);
    cudaGetSymbolAddress((void**)&mu, g_mu);
    cudaGetSymbolAddress((void**)&istd, g_istd);

    const int TB = 256;
    const int N = N_NODES, E = N_EDGES, G = G_GRAPHS;

    // zero concat buffer (pooling accumulates into it)
    fill_kernel<<<ceil_div((long long)G * CCOLS, TB), TB>>>(cbuf, 0.0f, (size_t)G * CCOLS);

    for (int t = 0; t < 2; t++) {
        const int* rows = ei[t];
        const int* cols = ei[t] + E;

        // degree (init 1.0 for self loop) -> dinv
        fill_kernel<<<ceil_div(N, TB), TB>>>(dinv, 1.0f, (size_t)N);
        deg_accum_kernel<<<ceil_div(E, TB), TB>>>(cols, dinv, E);
        rsqrt_kernel<<<ceil_div(N, TB), TB>>>(dinv, N);

        // ---- layer 1: aggregate x at 128 dims, then GEMM+bias+relu -> bufB[N,256]
        self_init_kernel<128><<<ceil_div((long long)N * 32, TB), TB>>>(x[t], bufA, dinv, N);
        agg_kernel<128><<<ceil_div(E, 8), TB>>>(x[t], bufA, rows, cols, dinv, E);
        gemm_kernel<true, true><<<dim3(256 / 64, N / 64), 256>>>(bufA, Wc1, bc1, bufB, N, 128, 256, 256, 0);

        // ---- layer 2
        self_init_kernel<256><<<ceil_div((long long)N * 64, TB), TB>>>(bufB, bufA, dinv, N);
        agg_kernel<256><<<ceil_div(E, 8), TB>>>(bufB, bufA, rows, cols, dinv, E);
        gemm_kernel<true, true><<<dim3(256 / 64, N / 64), 256>>>(bufA, Wc2, bc2, bufB, N, 256, 256, 256, 0);

        // ---- layer 3
        self_init_kernel<256><<<ceil_div((long long)N * 64, TB), TB>>>(bufB, bufA, dinv, N);
        agg_kernel<256><<<ceil_div(E, 8), TB>>>(bufB, bufA, rows, cols, dinv, E);
        gemm_kernel<true, true><<<dim3(256 / 64, N / 64), 256>>>(bufA, Wc3, bc3, bufB, N, 256, 256, 256, 0);

        // ---- layer 4: GEMM first (no bias/relu), aggregate at 128 dims
        gemm_kernel<false, false><<<dim3(128 / 64, N / 64), 256>>>(bufB, Wc4, (const float*)0, bufA, N, 256, 128, 128, 0);
        self_init_kernel<128><<<ceil_div((long long)N * 32, TB), TB>>>(bufA, bufB, dinv, N);
        agg_kernel<128><<<ceil_div(E, 8), TB>>>(bufA, bufB, rows, cols, dinv, E);

        // ---- mean pool (bias+relu fused) into c[:, t*128 : t*128+128]
        fill_kernel<<<ceil_div(G, TB), TB>>>(cnt, 0.0f, (size_t)G);
        count_kernel<<<ceil_div(N, TB), TB>>>(batch[t], cnt, N);
        pool_kernel<<<ceil_div((long long)N * 32, TB), TB>>>(bufB, batch[t], bc4, cbuf, t * H2, N);
        pool_div_kernel<<<ceil_div(G * H2, TB), TB>>>(cbuf, cnt, t * H2);

        // ---- notes MLP into c[:, 256 + t*128 : ...]
        gemm_kernel<true, true><<<dim3(256 / 64, G / 64), 256>>>(notes[t], Wn1, bn1b, t1, G, 128, 256, 256, 0);
        gemm_kernel<true, true><<<dim3(128 / 64, G / 64), 256>>>(t1, Wn2, bn2b, cbuf, G, 256, 128, CCOLS, 256 + t * H2);
    }

    // ---- head: f1 = BN(relu(c @ Wf1 + bf1))
    gemm_kernel<true, true><<<dim3(256 / 64, G / 64), 256>>>(cbuf, Wf1, bf1, t1, G, 512, 256, 256, 0);
    bn_stats_kernel<<<256, 256>>>(t1, 256, mu, istd);
    bn_apply_kernel<<<ceil_div((long long)G * 256, TB), TB>>>(t1, mu, istd, g1, be1, 256, G * 256);

    // f2 = BN(relu(f1 @ Wf2 + bf2))
    gemm_kernel<true, true><<<dim3(128 / 64, G / 64), 256>>>(t1, Wf2, bf2, t2, G, 256, 128, 128, 0);
    bn_stats_kernel<<<128, 256>>>(t2, 128, mu, istd);
    bn_apply_kernel<<<ceil_div((long long)G * 128, TB), TB>>>(t2, mu, istd, g2, be2, 128, G * 128);

    // out = f2 @ Wf3 + bf3
    gemm_kernel<false, true><<<dim3(128 / 64, G / 64), 256>>>(t2, Wf3, bf3, (float*)d_out, G, 128, 128, 128, 0);
}

// round 3
// speedup vs baseline: 1.7539x; 1.1102x over previous
#include <cuda_runtime.h>
#include <math.h>
#include <stdint.h>

#define N_NODES 200000
#define N_PAD   200064          // padded to multiple of 128 for TC GEMM
#define N_EDGES 3200000
#define G_GRAPHS 8192
#define HID 256
#define H2 128
#define CCOLS 512
#define EPS 1e-5f

// ---------------- scratch (device globals; no runtime alloc) ----------------
__device__ float g_bufA[(size_t)N_PAD * HID];
__device__ float g_bufB[(size_t)N_PAD * HID];
__device__ float g_dinv[N_NODES];
__device__ float g_cnt[G_GRAPHS];
__device__ float g_c[(size_t)G_GRAPHS * CCOLS];
__device__ float g_t1[(size_t)G_GRAPHS * HID];
__device__ float g_t2[(size_t)G_GRAPHS * H2];
__device__ float g_mu[HID];
__device__ float g_istd[HID];

// vectorized fp32 reduction to global memory (sm_90+)
__device__ __forceinline__ void red_add_v4(float* addr, float4 v) {
    asm volatile("red.global.add.v4.f32 [%0], {%1, %2, %3, %4};"
                 :: "l"(addr), "f"(v.x), "f"(v.y), "f"(v.z), "f"(v.w)
                 : "memory");
}

// ---------------- utility kernels ----------------
__global__ void fill_kernel(float* __restrict__ p, float v, size_t n) {
    size_t i = (size_t)blockIdx.x * blockDim.x + threadIdx.x;
    if (i < n) p[i] = v;
}

__global__ void deg_accum_kernel(const int* __restrict__ cols, float* __restrict__ deg, int nE) {
    int i = blockIdx.x * blockDim.x + threadIdx.x;
    if (i < nE) atomicAdd(&deg[cols[i]], 1.0f);
}

__global__ void rsqrt_kernel(float* __restrict__ d, int n) {
    int i = blockIdx.x * blockDim.x + threadIdx.x;
    if (i < n) d[i] = rsqrtf(d[i]);
}

// out[i,:] = in[i,:] * dinv[i]^2   (self-loop term, also serves as the zero-init)
template <int D>
__global__ void self_init_kernel(const float* __restrict__ in, float* __restrict__ out,
                                 const float* __restrict__ dinv, int n) {
    size_t idx = (size_t)blockIdx.x * blockDim.x + threadIdx.x;
    if (idx >= (size_t)n * (D / 4)) return;
    int i = (int)(idx / (D / 4));
    float w = dinv[i];
    w = w * w;
    float4 v = ((const float4*)in)[idx];
    v.x *= w; v.y *= w; v.z *= w; v.w *= w;
    ((float4*)out)[idx] = v;
}

// one warp per edge: out[col,:] += in[row,:] * dinv[row]*dinv[col]
template <int D>
__global__ void agg_kernel(const float* __restrict__ in, float* __restrict__ out,
                           const int* __restrict__ rows, const int* __restrict__ cols,
                           const float* __restrict__ dinv, int nE) {
    int e = blockIdx.x * (blockDim.x >> 5) + (threadIdx.x >> 5);
    if (e >= nE) return;
    int lane = threadIdx.x & 31;
    int r = rows[e], c = cols[e];
    float w = dinv[r] * dinv[c];
    const float4* src = (const float4*)(in + (size_t)r * D);
    float4* dst = (float4*)(out + (size_t)c * D);
#pragma unroll
    for (int v = 0; v < D / 128; v++) {
        float4 x = src[lane + v * 32];
        x.x *= w; x.y *= w; x.z *= w; x.w *= w;
        red_add_v4((float*)&dst[lane + v * 32], x);
    }
}

__global__ void count_kernel(const int* __restrict__ batch, float* __restrict__ cnt, int n) {
    int i = blockIdx.x * blockDim.x + threadIdx.x;
    if (i < n) atomicAdd(&cnt[batch[i]], 1.0f);
}

// c[batch[i], coff+d..d+3] += relu(buf[i,d..d+3] + bias[d..d+3])
__global__ void pool_kernel(const float* __restrict__ buf, const int* __restrict__ batch,
                            const float* __restrict__ bias, float* __restrict__ c,
                            int coff, int n) {
    size_t idx = (size_t)blockIdx.x * blockDim.x + threadIdx.x;  // over n * 32
    if (idx >= (size_t)n * 32) return;
    int i = (int)(idx >> 5);
    int d4 = (int)(idx & 31) * 4;
    float4 v = *(const float4*)&buf[(size_t)i * H2 + d4];
    float4 b = *(const float4*)&bias[d4];
    v.x = fmaxf(v.x + b.x, 0.0f);
    v.y = fmaxf(v.y + b.y, 0.0f);
    v.z = fmaxf(v.z + b.z, 0.0f);
    v.w = fmaxf(v.w + b.w, 0.0f);
    red_add_v4(&c[(size_t)batch[i] * CCOLS + coff + d4], v);
}

__global__ void pool_div_kernel(float* __restrict__ c, const float* __restrict__ cnt, int coff) {
    int idx = blockIdx.x * blockDim.x + threadIdx.x;
    if (idx >= G_GRAPHS * H2) return;
    int g = idx >> 7, d = idx & 127;
    c[(size_t)g * CCOLS + coff + d] *= 1.0f / fmaxf(cnt[g], 1.0f);
}

// ---------------- tensor-core GEMM (3xTF32 split => fp32 accuracy) ----------------
// C[M,N] = (relu)(A[M,K] @ W[K,N] (+bias)), A row-major (lda=K), W row-major (ldw=N).
// BM=128, BN=64, BK=16; 256 threads = 8 warps (4 along M, 2 along N), 32x32 warp tile.
// M % 128 == 0 (callers pad), N % 64 == 0, K % 16 == 0.

__device__ __forceinline__ void tf32_split(float x, uint32_t& h, uint32_t& l) {
    asm("cvt.rna.tf32.f32 %0, %1;" : "=r"(h) : "f"(x));
    float r = x - __uint_as_float(h);
    asm("cvt.rna.tf32.f32 %0, %1;" : "=r"(l) : "f"(r));
}

__device__ __forceinline__ void mma_tf32(float* c,
                                         uint32_t a0, uint32_t a1, uint32_t a2, uint32_t a3,
                                         uint32_t b0, uint32_t b1) {
    asm volatile(
        "mma.sync.aligned.m16n8k8.row.col.f32.tf32.tf32.f32 "
        "{%0,%1,%2,%3}, {%4,%5,%6,%7}, {%8,%9}, {%0,%1,%2,%3};"
        : "+f"(c[0]), "+f"(c[1]), "+f"(c[2]), "+f"(c[3])
        : "r"(a0), "r"(a1), "r"(a2), "r"(a3), "r"(b0), "r"(b1));
}

template <bool RELU, bool BIAS>
__global__ __launch_bounds__(256) void tc_gemm(
    const float* __restrict__ A, const float* __restrict__ W,
    const float* __restrict__ bias, float* __restrict__ C,
    int M, int K, int N, int ldc, int coff) {
    // strides chosen conflict-free: As stride 20 (20g+tig covers all banks),
    // Bs stride 72 (8*tig+g covers all banks)
    __shared__ float As[128][20];
    __shared__ float Bs[16][72];

    int tid = threadIdx.x;
    int bm = blockIdx.y * 128, bn = blockIdx.x * 64;
    int warp = tid >> 5, lane = tid & 31;
    int wm = (warp & 3) * 32, wn = (warp >> 2) * 32;
    int g = lane >> 2, tig = lane & 3;

    float acc[2][4][4] = {};

    for (int k0 = 0; k0 < K; k0 += 16) {
        // ---- load A tile (128x16) : 2 float4 per thread
#pragma unroll
        for (int i = 0; i < 2; i++) {
            int idx = tid + i * 256;
            int row = idx >> 2, c4 = (idx & 3) << 2;
            float4 v = *(const float4*)&A[(size_t)(bm + row) * K + k0 + c4];
            As[row][c4 + 0] = v.x; As[row][c4 + 1] = v.y;
            As[row][c4 + 2] = v.z; As[row][c4 + 3] = v.w;
        }
        // ---- load W tile (16x64) : 1 float4 per thread
        {
            int row = tid >> 4, c4 = (tid & 15) << 2;
            float4 v = *(const float4*)&W[(size_t)(k0 + row) * N + bn + c4];
            Bs[row][c4 + 0] = v.x; Bs[row][c4 + 1] = v.y;
            Bs[row][c4 + 2] = v.z; Bs[row][c4 + 3] = v.w;
        }
        __syncthreads();

#pragma unroll
        for (int k8 = 0; k8 < 16; k8 += 8) {
            uint32_t ah[2][4], al[2][4], bh[4][2], bl[4][2];
#pragma unroll
            for (int mt = 0; mt < 2; mt++) {
                int m = wm + mt * 16 + g;
                tf32_split(As[m][k8 + tig],         ah[mt][0], al[mt][0]);
                tf32_split(As[m + 8][k8 + tig],     ah[mt][1], al[mt][1]);
                tf32_split(As[m][k8 + tig + 4],     ah[mt][2], al[mt][2]);
                tf32_split(As[m + 8][k8 + tig + 4], ah[mt][3], al[mt][3]);
            }
#pragma unroll
            for (int nt = 0; nt < 4; nt++) {
                int n = wn + nt * 8 + g;
                tf32_split(Bs[k8 + tig][n],     bh[nt][0], bl[nt][0]);
                tf32_split(Bs[k8 + tig + 4][n], bh[nt][1], bl[nt][1]);
            }
#pragma unroll
            for (int mt = 0; mt < 2; mt++)
#pragma unroll
                for (int nt = 0; nt < 4; nt++) {
                    mma_tf32(acc[mt][nt], ah[mt][0], ah[mt][1], ah[mt][2], ah[mt][3],
                             bh[nt][0], bh[nt][1]);
                    mma_tf32(acc[mt][nt], ah[mt][0], ah[mt][1], ah[mt][2], ah[mt][3],
                             bl[nt][0], bl[nt][1]);
                    mma_tf32(acc[mt][nt], al[mt][0], al[mt][1], al[mt][2], al[mt][3],
                             bh[nt][0], bh[nt][1]);
                }
        }
        __syncthreads();
    }

    // ---- epilogue
#pragma unroll
    for (int mt = 0; mt < 2; mt++) {
        int row0 = bm + wm + mt * 16 + g;
#pragma unroll
        for (int nt = 0; nt < 4; nt++) {
            int col = bn + wn + nt * 8 + 2 * tig;
            float b0 = 0.f, b1 = 0.f;
            if (BIAS) { b0 = bias[col]; b1 = bias[col + 1]; }
            float v0 = acc[mt][nt][0] + b0;
            float v1 = acc[mt][nt][1] + b1;
            float v2 = acc[mt][nt][2] + b0;
            float v3 = acc[mt][nt][3] + b1;
            if (RELU) {
                v0 = fmaxf(v0, 0.f); v1 = fmaxf(v1, 0.f);
                v2 = fmaxf(v2, 0.f); v3 = fmaxf(v3, 0.f);
            }
            *(float2*)&C[(size_t)row0 * ldc + coff + col] = make_float2(v0, v1);
            *(float2*)&C[(size_t)(row0 + 8) * ldc + coff + col] = make_float2(v2, v3);
        }
    }
}

// ---------------- batch norm ----------------
__global__ void bn_stats_kernel(const float* __restrict__ X, int C,
                                float* __restrict__ mu, float* __restrict__ istd) {
    int c = blockIdx.x;
    int tid = threadIdx.x;
    float s = 0.f, s2 = 0.f;
    for (int r = tid; r < G_GRAPHS; r += 256) {
        float v = X[(size_t)r * C + c];
        s += v;
        s2 += v * v;
    }
    __shared__ float sh[256], sh2[256];
    sh[tid] = s;
    sh2[tid] = s2;
    __syncthreads();
    for (int o = 128; o > 0; o >>= 1) {
        if (tid < o) {
            sh[tid] += sh[tid + o];
            sh2[tid] += sh2[tid + o];
        }
        __syncthreads();
    }
    if (tid == 0) {
        float m = sh[0] / (float)G_GRAPHS;
        float var = sh2[0] / (float)G_GRAPHS - m * m;
        mu[c] = m;
        istd[c] = rsqrtf(var + EPS);
    }
}

__global__ void bn_apply_kernel(float* __restrict__ X, const float* __restrict__ mu,
                                const float* __restrict__ istd, const float* __restrict__ gamma,
                                const float* __restrict__ beta, int C, int total) {
    int idx = blockIdx.x * blockDim.x + threadIdx.x;
    if (idx >= total) return;
    int c = idx % C;
    X[idx] = (X[idx] - mu[c]) * istd[c] * gamma[c] + beta[c];
}

// ---------------- host launcher ----------------
static inline int ceil_div(long long a, int b) { return (int)((a + b - 1) / b); }

extern "C" void kernel_launch(void* const* d_in, const int* in_sizes, int n_in,
                              void* d_out, int out_size) {
    const float* x[2] = {(const float*)d_in[0], (const float*)d_in[1]};
    const int* ei[2] = {(const int*)d_in[2], (const int*)d_in[3]};
    const int* batch[2] = {(const int*)d_in[4], (const int*)d_in[5]};
    const float* notes[2] = {(const float*)d_in[6], (const float*)d_in[7]};
    const float* Wc1 = (const float*)d_in[8];  const float* bc1 = (const float*)d_in[9];
    const float* Wc2 = (const float*)d_in[10]; const float* bc2 = (const float*)d_in[11];
    const float* Wc3 = (const float*)d_in[12]; const float* bc3 = (const float*)d_in[13];
    const float* Wc4 = (const float*)d_in[14]; const float* bc4 = (const float*)d_in[15];
    const float* Wn1 = (const float*)d_in[16]; const float* bn1b = (const float*)d_in[17];
    const float* Wn2 = (const float*)d_in[18]; const float* bn2b = (const float*)d_in[19];
    const float* Wf1 = (const float*)d_in[20]; const float* bf1 = (const float*)d_in[21];
    const float* g1 = (const float*)d_in[22];  const float* be1 = (const float*)d_in[23];
    const float* Wf2 = (const float*)d_in[24]; const float* bf2 = (const float*)d_in[25];
    const float* g2 = (const float*)d_in[26];  const float* be2 = (const float*)d_in[27];
    const float* Wf3 = (const float*)d_in[28]; const float* bf3 = (const float*)d_in[29];

    float *bufA, *bufB, *dinv, *cnt, *cbuf, *t1, *t2, *mu, *istd;
    cudaGetSymbolAddress((void**)&bufA, g_bufA);
    cudaGetSymbolAddress((void**)&bufB, g_bufB);
    cudaGetSymbolAddress((void**)&dinv, g_dinv);
    cudaGetSymbolAddress((void**)&cnt, g_cnt);
    cudaGetSymbolAddress((void**)&cbuf, g_c);
    cudaGetSymbolAddress((void**)&t1, g_t1);
    cudaGetSymbolAddress((void**)&t2, g_t2);
    cudaGetSymbolAddress((void**)&mu, g_mu);
    cudaGetSymbolAddress((void**)&istd, g_istd);

    const int TB = 256;
    const int N = N_NODES, E = N_EDGES, G = G_GRAPHS;
    const int MPAD = N_PAD;
    const int PADR = N_PAD - N_NODES;  // 64 pad rows

    // zero concat buffer (pooling accumulates into it)
    fill_kernel<<<ceil_div((long long)G * CCOLS, TB), TB>>>(cbuf, 0.0f, (size_t)G * CCOLS);
    // zero pad regions (determinism: every replay starts from the same pad state)
    fill_kernel<<<ceil_div((long long)PADR * 128, TB), TB>>>(bufA + (size_t)N * 128, 0.0f, (size_t)PADR * 128);
    fill_kernel<<<ceil_div((long long)PADR * 256, TB), TB>>>(bufA + (size_t)N * 256, 0.0f, (size_t)PADR * 256);
    fill_kernel<<<ceil_div((long long)PADR * 128, TB), TB>>>(bufB + (size_t)N * 128, 0.0f, (size_t)PADR * 128);
    fill_kernel<<<ceil_div((long long)PADR * 256, TB), TB>>>(bufB + (size_t)N * 256, 0.0f, (size_t)PADR * 256);

    for (int t = 0; t < 2; t++) {
        const int* rows = ei[t];
        const int* cols = ei[t] + E;

        // degree (init 1.0 for self loop) -> dinv
        fill_kernel<<<ceil_div(N, TB), TB>>>(dinv, 1.0f, (size_t)N);
        deg_accum_kernel<<<ceil_div(E, TB), TB>>>(cols, dinv, E);
        rsqrt_kernel<<<ceil_div(N, TB), TB>>>(dinv, N);

        // ---- layer 1: aggregate x at 128 dims, then GEMM+bias+relu -> bufB[N,256]
        self_init_kernel<128><<<ceil_div((long long)N * 32, TB), TB>>>(x[t], bufA, dinv, N);
        agg_kernel<128><<<ceil_div(E, 8), TB>>>(x[t], bufA, rows, cols, dinv, E);
        tc_gemm<true, true><<<dim3(256 / 64, MPAD / 128), 256>>>(bufA, Wc1, bc1, bufB, MPAD, 128, 256, 256, 0);

        // ---- layer 2
        self_init_kernel<256><<<ceil_div((long long)N * 64, TB), TB>>>(bufB, bufA, dinv, N);
        agg_kernel<256><<<ceil_div(E, 8), TB>>>(bufB, bufA, rows, cols, dinv, E);
        tc_gemm<true, true><<<dim3(256 / 64, MPAD / 128), 256>>>(bufA, Wc2, bc2, bufB, MPAD, 256, 256, 256, 0);

        // ---- layer 3
        self_init_kernel<256><<<ceil_div((long long)N * 64, TB), TB>>>(bufB, bufA, dinv, N);
        agg_kernel<256><<<ceil_div(E, 8), TB>>>(bufB, bufA, rows, cols, dinv, E);
        tc_gemm<true, true><<<dim3(256 / 64, MPAD / 128), 256>>>(bufA, Wc3, bc3, bufB, MPAD, 256, 256, 256, 0);

        // ---- layer 4: GEMM first (no bias/relu), aggregate at 128 dims
        tc_gemm<false, false><<<dim3(128 / 64, MPAD / 128), 256>>>(bufB, Wc4, (const float*)0, bufA, MPAD, 256, 128, 128, 0);
        self_init_kernel<128><<<ceil_div((long long)N * 32, TB), TB>>>(bufA, bufB, dinv, N);
        agg_kernel<128><<<ceil_div(E, 8), TB>>>(bufA, bufB, rows, cols, dinv, E);

        // ---- mean pool (bias+relu fused) into c[:, t*128 : t*128+128]
        fill_kernel<<<ceil_div(G, TB), TB>>>(cnt, 0.0f, (size_t)G);
        count_kernel<<<ceil_div(N, TB), TB>>>(batch[t], cnt, N);
        pool_kernel<<<ceil_div((long long)N * 32, TB), TB>>>(bufB, batch[t], bc4, cbuf, t * H2, N);
        pool_div_kernel<<<ceil_div(G * H2, TB), TB>>>(cbuf, cnt, t * H2);

        // ---- notes MLP into c[:, 256 + t*128 : ...]
        tc_gemm<true, true><<<dim3(256 / 64, G / 128), 256>>>(notes[t], Wn1, bn1b, t1, G, 128, 256, 256, 0);
        tc_gemm<true, true><<<dim3(128 / 64, G / 128), 256>>>(t1, Wn2, bn2b, cbuf, G, 256, 128, CCOLS, 256 + t * H2);
    }

    // ---- head: f1 = BN(relu(c @ Wf1 + bf1))
    tc_gemm<true, true><<<dim3(256 / 64, G / 128), 256>>>(cbuf, Wf1, bf1, t1, G, 512, 256, 256, 0);
    bn_stats_kernel<<<256, 256>>>(t1, 256, mu, istd);
    bn_apply_kernel<<<ceil_div((long long)G * 256, TB), TB>>>(t1, mu, istd, g1, be1, 256, G * 256);

    // f2 = BN(relu(f1 @ Wf2 + bf2))
    tc_gemm<true, true><<<dim3(128 / 64, G / 128), 256>>>(t1, Wf2, bf2, t2, G, 256, 128, 128, 0);
    bn_stats_kernel<<<128, 256>>>(t2, 128, mu, istd);
    bn_apply_kernel<<<ceil_div((long long)G * 128, TB), TB>>>(t2, mu, istd, g2, be2, 128, G * 128);

    // out = f2 @ Wf3 + bf3
    tc_gemm<false, true><<<dim3(128 / 64, G / 128), 256>>>(t2, Wf3, bf3, (float*)d_out, G, 128, 128, 128, 0);
}

// round 4
// speedup vs baseline: 3.1459x; 1.7937x over previous
#include <cuda_runtime.h>
#include <math.h>
#include <stdint.h>

#define N_NODES 200000
#define N_PAD   200064          // padded to multiple of 128 for TC GEMM
#define N_EDGES 3200000
#define G_GRAPHS 8192
#define HID 256
#define H2 128
#define CCOLS 512
#define EPS 1e-5f
#define SCAN_CHUNK 2048

// ---------------- scratch (device globals; no runtime alloc) ----------------
__device__ float g_bufA[(size_t)N_PAD * HID];
__device__ float g_bufB[(size_t)N_PAD * HID];
__device__ float g_dinv[N_NODES];
__device__ int   g_deg[N_NODES];
__device__ int   g_off[N_NODES];
__device__ int   g_cur[N_NODES];
__device__ int   g_bsum[256];
__device__ int   g_ridx[N_EDGES];
__device__ float g_wsrc[N_EDGES];
__device__ float g_cnt[G_GRAPHS];
__device__ float g_c[(size_t)G_GRAPHS * CCOLS];
__device__ float g_t1[(size_t)G_GRAPHS * HID];
__device__ float g_t2[(size_t)G_GRAPHS * H2];
__device__ float g_mu[HID];
__device__ float g_istd[HID];

// vectorized fp32 reduction to global memory (sm_90+)
__device__ __forceinline__ void red_add_v4(float* addr, float4 v) {
    asm volatile("red.global.add.v4.f32 [%0], {%1, %2, %3, %4};"
                 :: "l"(addr), "f"(v.x), "f"(v.y), "f"(v.z), "f"(v.w)
                 : "memory");
}

// ---------------- utility kernels ----------------
__global__ void fill_kernel(float* __restrict__ p, float v, size_t n) {
    size_t i = (size_t)blockIdx.x * blockDim.x + threadIdx.x;
    if (i < n) p[i] = v;
}

__global__ void zero_int_kernel(int* __restrict__ p, int n) {
    int i = blockIdx.x * blockDim.x + threadIdx.x;
    if (i < n) p[i] = 0;
}

__global__ void hist_kernel(const int* __restrict__ cols, int* __restrict__ deg, int nE) {
    int i = blockIdx.x * blockDim.x + threadIdx.x;
    if (i < nE) atomicAdd(&deg[cols[i]], 1);
}

__global__ void dinv_kernel(const int* __restrict__ deg, float* __restrict__ dinv, int n) {
    int i = blockIdx.x * blockDim.x + threadIdx.x;
    if (i < n) dinv[i] = rsqrtf((float)deg[i] + 1.0f);  // +1 for self loop
}

// ---------------- exclusive scan (3-phase) over g_deg -> g_off, g_cur ----------------
__global__ void scan_partial_kernel(const int* __restrict__ deg, int* __restrict__ bsum, int n) {
    __shared__ int sh[256];
    int t = threadIdx.x;
    int base = blockIdx.x * SCAN_CHUNK + t * 8;
    int s = 0;
#pragma unroll
    for (int k = 0; k < 8; k++)
        if (base + k < n) s += deg[base + k];
    sh[t] = s;
    __syncthreads();
    for (int o = 128; o > 0; o >>= 1) {
        if (t < o) sh[t] += sh[t + o];
        __syncthreads();
    }
    if (t == 0) bsum[blockIdx.x] = sh[0];
}

__global__ void scan_top_kernel(int* __restrict__ bsum, int nb) {
    __shared__ int sh[256];
    int t = threadIdx.x;
    int v = (t < nb) ? bsum[t] : 0;
    sh[t] = v;
    __syncthreads();
    for (int o = 1; o < 256; o <<= 1) {
        int x = (t >= o) ? sh[t - o] : 0;
        __syncthreads();
        sh[t] += x;
        __syncthreads();
    }
    if (t < nb) bsum[t] = sh[t] - v;  // exclusive
}

__global__ void scan_apply_kernel(const int* __restrict__ deg, const int* __restrict__ bsum,
                                  int* __restrict__ off, int* __restrict__ cur, int n) {
    __shared__ int sh[256];
    int t = threadIdx.x;
    int base = blockIdx.x * SCAN_CHUNK + t * 8;
    int loc[8];
    int s = 0;
#pragma unroll
    for (int k = 0; k < 8; k++) {
        loc[k] = (base + k < n) ? deg[base + k] : 0;
        s += loc[k];
    }
    sh[t] = s;
    __syncthreads();
    for (int o = 1; o < 256; o <<= 1) {
        int x = (t >= o) ? sh[t - o] : 0;
        __syncthreads();
        sh[t] += x;
        __syncthreads();
    }
    int run = bsum[blockIdx.x] + sh[t] - s;
#pragma unroll
    for (int k = 0; k < 8; k++) {
        if (base + k < n) {
            off[base + k] = run;
            cur[base + k] = run;
            run += loc[k];
        }
    }
}

__global__ void csr_fill_kernel(const int* __restrict__ rows, const int* __restrict__ cols,
                                const float* __restrict__ dinv, int* __restrict__ cur,
                                int* __restrict__ ridx, float* __restrict__ wsrc, int nE) {
    int e = blockIdx.x * blockDim.x + threadIdx.x;
    if (e >= nE) return;
    int c = cols[e], r = rows[e];
    int p = atomicAdd(&cur[c], 1);
    ridx[p] = r;
    wsrc[p] = dinv[r];
}

// ---------------- CSR gather aggregation (pull; no scatter atomics) ----------------
// out[i,:] = dinv[i] * ( sum_{r in in(i)} dinv[r]*in[r,:] + dinv[i]*in[i,:] )
// one warp per destination node. If POOL: instead of writing out, do
// red_add(cbuf[batch[i]*CCOLS+coff], relu(acc + bias)).
template <int D, bool POOL>
__global__ __launch_bounds__(256) void agg_csr_kernel(
    const float* __restrict__ in, float* __restrict__ out,
    const int* __restrict__ off, const int* __restrict__ ridx,
    const float* __restrict__ wsrc, const float* __restrict__ dinv,
    const int* __restrict__ batch, const float* __restrict__ bias,
    float* __restrict__ cbuf, int coff, int n) {
    int node = blockIdx.x * (blockDim.x >> 5) + (threadIdx.x >> 5);
    if (node >= n) return;
    int lane = threadIdx.x & 31;
    int s = off[node];
    int e = (node == n - 1) ? N_EDGES : off[node + 1];
    float dc = dinv[node];

    constexpr int V = D / 128;
    float4 acc[V];
    // self term (weight dc; whole acc scaled by dc at the end)
    const float4* selfp = (const float4*)(in + (size_t)node * D);
#pragma unroll
    for (int v = 0; v < V; v++) {
        float4 x = selfp[lane + v * 32];
        acc[v].x = x.x * dc; acc[v].y = x.y * dc;
        acc[v].z = x.z * dc; acc[v].w = x.w * dc;
    }
    for (int j = s; j < e; j++) {
        int r = ridx[j];
        float w = wsrc[j];
        const float4* src = (const float4*)(in + (size_t)r * D);
#pragma unroll
        for (int v = 0; v < V; v++) {
            float4 x = src[lane + v * 32];
            acc[v].x += x.x * w; acc[v].y += x.y * w;
            acc[v].z += x.z * w; acc[v].w += x.w * w;
        }
    }
#pragma unroll
    for (int v = 0; v < V; v++) {
        acc[v].x *= dc; acc[v].y *= dc; acc[v].z *= dc; acc[v].w *= dc;
    }

    if (POOL) {
        float4 b = *(const float4*)&bias[lane * 4];
        float4 v0;
        v0.x = fmaxf(acc[0].x + b.x, 0.0f);
        v0.y = fmaxf(acc[0].y + b.y, 0.0f);
        v0.z = fmaxf(acc[0].z + b.z, 0.0f);
        v0.w = fmaxf(acc[0].w + b.w, 0.0f);
        red_add_v4(&cbuf[(size_t)batch[node] * CCOLS + coff + lane * 4], v0);
    } else {
        float4* dst = (float4*)(out + (size_t)node * D);
#pragma unroll
        for (int v = 0; v < V; v++) dst[lane + v * 32] = acc[v];
    }
}

__global__ void count_kernel(const int* __restrict__ batch, float* __restrict__ cnt, int n) {
    int i = blockIdx.x * blockDim.x + threadIdx.x;
    if (i < n) atomicAdd(&cnt[batch[i]], 1.0f);
}

__global__ void pool_div_kernel(float* __restrict__ c, const float* __restrict__ cnt, int coff) {
    int idx = blockIdx.x * blockDim.x + threadIdx.x;
    if (idx >= G_GRAPHS * H2) return;
    int g = idx >> 7, d = idx & 127;
    c[(size_t)g * CCOLS + coff + d] *= 1.0f / fmaxf(cnt[g], 1.0f);
}

// ---------------- tensor-core GEMM (3xTF32 split => fp32 accuracy) ----------------
__device__ __forceinline__ void tf32_split(float x, uint32_t& h, uint32_t& l) {
    asm("cvt.rna.tf32.f32 %0, %1;" : "=r"(h) : "f"(x));
    float r = x - __uint_as_float(h);
    asm("cvt.rna.tf32.f32 %0, %1;" : "=r"(l) : "f"(r));
}

__device__ __forceinline__ void mma_tf32(float* c,
                                         uint32_t a0, uint32_t a1, uint32_t a2, uint32_t a3,
                                         uint32_t b0, uint32_t b1) {
    asm volatile(
        "mma.sync.aligned.m16n8k8.row.col.f32.tf32.tf32.f32 "
        "{%0,%1,%2,%3}, {%4,%5,%6,%7}, {%8,%9}, {%0,%1,%2,%3};"
        : "+f"(c[0]), "+f"(c[1]), "+f"(c[2]), "+f"(c[3])
        : "r"(a0), "r"(a1), "r"(a2), "r"(a3), "r"(b0), "r"(b1));
}

template <bool RELU, bool BIAS>
__global__ __launch_bounds__(256) void tc_gemm(
    const float* __restrict__ A, const float* __restrict__ W,
    const float* __restrict__ bias, float* __restrict__ C,
    int M, int K, int N, int ldc, int coff) {
    __shared__ float As[128][20];
    __shared__ float Bs[16][72];

    int tid = threadIdx.x;
    int bm = blockIdx.y * 128, bn = blockIdx.x * 64;
    int warp = tid >> 5, lane = tid & 31;
    int wm = (warp & 3) * 32, wn = (warp >> 2) * 32;
    int g = lane >> 2, tig = lane & 3;

    float acc[2][4][4] = {};

    for (int k0 = 0; k0 < K; k0 += 16) {
#pragma unroll
        for (int i = 0; i < 2; i++) {
            int idx = tid + i * 256;
            int row = idx >> 2, c4 = (idx & 3) << 2;
            float4 v = *(const float4*)&A[(size_t)(bm + row) * K + k0 + c4];
            As[row][c4 + 0] = v.x; As[row][c4 + 1] = v.y;
            As[row][c4 + 2] = v.z; As[row][c4 + 3] = v.w;
        }
        {
            int row = tid >> 4, c4 = (tid & 15) << 2;
            float4 v = *(const float4*)&W[(size_t)(k0 + row) * N + bn + c4];
            Bs[row][c4 + 0] = v.x; Bs[row][c4 + 1] = v.y;
            Bs[row][c4 + 2] = v.z; Bs[row][c4 + 3] = v.w;
        }
        __syncthreads();

#pragma unroll
        for (int k8 = 0; k8 < 16; k8 += 8) {
            uint32_t ah[2][4], al[2][4], bh[4][2], bl[4][2];
#pragma unroll
            for (int mt = 0; mt < 2; mt++) {
                int m = wm + mt * 16 + g;
                tf32_split(As[m][k8 + tig],         ah[mt][0], al[mt][0]);
                tf32_split(As[m + 8][k8 + tig],     ah[mt][1], al[mt][1]);
                tf32_split(As[m][k8 + tig + 4],     ah[mt][2], al[mt][2]);
                tf32_split(As[m + 8][k8 + tig + 4], ah[mt][3], al[mt][3]);
            }
#pragma unroll
            for (int nt = 0; nt < 4; nt++) {
                int n = wn + nt * 8 + g;
                tf32_split(Bs[k8 + tig][n],     bh[nt][0], bl[nt][0]);
                tf32_split(Bs[k8 + tig + 4][n], bh[nt][1], bl[nt][1]);
            }
#pragma unroll
            for (int mt = 0; mt < 2; mt++)
#pragma unroll
                for (int nt = 0; nt < 4; nt++) {
                    mma_tf32(acc[mt][nt], ah[mt][0], ah[mt][1], ah[mt][2], ah[mt][3],
                             bh[nt][0], bh[nt][1]);
                    mma_tf32(acc[mt][nt], ah[mt][0], ah[mt][1], ah[mt][2], ah[mt][3],
                             bl[nt][0], bl[nt][1]);
                    mma_tf32(acc[mt][nt], al[mt][0], al[mt][1], al[mt][2], al[mt][3],
                             bh[nt][0], bh[nt][1]);
                }
        }
        __syncthreads();
    }

#pragma unroll
    for (int mt = 0; mt < 2; mt++) {
        int row0 = bm + wm + mt * 16 + g;
#pragma unroll
        for (int nt = 0; nt < 4; nt++) {
            int col = bn + wn + nt * 8 + 2 * tig;
            float b0 = 0.f, b1 = 0.f;
            if (BIAS) { b0 = bias[col]; b1 = bias[col + 1]; }
            float v0 = acc[mt][nt][0] + b0;
            float v1 = acc[mt][nt][1] + b1;
            float v2 = acc[mt][nt][2] + b0;
            float v3 = acc[mt][nt][3] + b1;
            if (RELU) {
                v0 = fmaxf(v0, 0.f); v1 = fmaxf(v1, 0.f);
                v2 = fmaxf(v2, 0.f); v3 = fmaxf(v3, 0.f);
            }
            *(float2*)&C[(size_t)row0 * ldc + coff + col] = make_float2(v0, v1);
            *(float2*)&C[(size_t)(row0 + 8) * ldc + coff + col] = make_float2(v2, v3);
        }
    }
}

// ---------------- batch norm ----------------
__global__ void bn_stats_kernel(const float* __restrict__ X, int C,
                                float* __restrict__ mu, float* __restrict__ istd) {
    int c = blockIdx.x;
    int tid = threadIdx.x;
    float s = 0.f, s2 = 0.f;
    for (int r = tid; r < G_GRAPHS; r += 256) {
        float v = X[(size_t)r * C + c];
        s += v;
        s2 += v * v;
    }
    __shared__ float sh[256], sh2[256];
    sh[tid] = s;
    sh2[tid] = s2;
    __syncthreads();
    for (int o = 128; o > 0; o >>= 1) {
        if (tid < o) {
            sh[tid] += sh[tid + o];
            sh2[tid] += sh2[tid + o];
        }
        __syncthreads();
    }
    if (tid == 0) {
        float m = sh[0] / (float)G_GRAPHS;
        float var = sh2[0] / (float)G_GRAPHS - m * m;
        mu[c] = m;
        istd[c] = rsqrtf(var + EPS);
    }
}

__global__ void bn_apply_kernel(float* __restrict__ X, const float* __restrict__ mu,
                                const float* __restrict__ istd, const float* __restrict__ gamma,
                                const float* __restrict__ beta, int C, int total) {
    int idx = blockIdx.x * blockDim.x + threadIdx.x;
    if (idx >= total) return;
    int c = idx % C;
    X[idx] = (X[idx] - mu[c]) * istd[c] * gamma[c] + beta[c];
}

// ---------------- host launcher ----------------
static inline int ceil_div(long long a, int b) { return (int)((a + b - 1) / b); }

extern "C" void kernel_launch(void* const* d_in, const int* in_sizes, int n_in,
                              void* d_out, int out_size) {
    const float* x[2] = {(const float*)d_in[0], (const float*)d_in[1]};
    const int* ei[2] = {(const int*)d_in[2], (const int*)d_in[3]};
    const int* batch[2] = {(const int*)d_in[4], (const int*)d_in[5]};
    const float* notes[2] = {(const float*)d_in[6], (const float*)d_in[7]};
    const float* Wc1 = (const float*)d_in[8];  const float* bc1 = (const float*)d_in[9];
    const float* Wc2 = (const float*)d_in[10]; const float* bc2 = (const float*)d_in[11];
    const float* Wc3 = (const float*)d_in[12]; const float* bc3 = (const float*)d_in[13];
    const float* Wc4 = (const float*)d_in[14]; const float* bc4 = (const float*)d_in[15];
    const float* Wn1 = (const float*)d_in[16]; const float* bn1b = (const float*)d_in[17];
    const float* Wn2 = (const float*)d_in[18]; const float* bn2b = (const float*)d_in[19];
    const float* Wf1 = (const float*)d_in[20]; const float* bf1 = (const float*)d_in[21];
    const float* g1 = (const float*)d_in[22];  const float* be1 = (const float*)d_in[23];
    const float* Wf2 = (const float*)d_in[24]; const float* bf2 = (const float*)d_in[25];
    const float* g2 = (const float*)d_in[26];  const float* be2 = (const float*)d_in[27];
    const float* Wf3 = (const float*)d_in[28]; const float* bf3 = (const float*)d_in[29];

    float *bufA, *bufB, *dinv, *cnt, *cbuf, *t1, *t2, *mu, *istd, *wsrc;
    int *deg, *off, *cur, *bsum, *ridx;
    cudaGetSymbolAddress((void**)&bufA, g_bufA);
    cudaGetSymbolAddress((void**)&bufB, g_bufB);
    cudaGetSymbolAddress((void**)&dinv, g_dinv);
    cudaGetSymbolAddress((void**)&deg, g_deg);
    cudaGetSymbolAddress((void**)&off, g_off);
    cudaGetSymbolAddress((void**)&cur, g_cur);
    cudaGetSymbolAddress((void**)&bsum, g_bsum);
    cudaGetSymbolAddress((void**)&ridx, g_ridx);
    cudaGetSymbolAddress((void**)&wsrc, g_wsrc);
    cudaGetSymbolAddress((void**)&cnt, g_cnt);
    cudaGetSymbolAddress((void**)&cbuf, g_c);
    cudaGetSymbolAddress((void**)&t1, g_t1);
    cudaGetSymbolAddress((void**)&t2, g_t2);
    cudaGetSymbolAddress((void**)&mu, g_mu);
    cudaGetSymbolAddress((void**)&istd, g_istd);

    const int TB = 256;
    const int N = N_NODES, E = N_EDGES, G = G_GRAPHS;
    const int MPAD = N_PAD;
    const int PADR = N_PAD - N_NODES;
    const int NB_SCAN = ceil_div(N, SCAN_CHUNK);   // 98
    const int AGG_BLK = ceil_div(N, 8);            // warp per node, 8 warps/block

    // zero concat buffer (pooling accumulates into it)
    fill_kernel<<<ceil_div((long long)G * CCOLS, TB), TB>>>(cbuf, 0.0f, (size_t)G * CCOLS);
    // zero pad rows (deterministic GEMM inputs each launch)
    fill_kernel<<<ceil_div((long long)PADR * 256, TB), TB>>>(bufA + (size_t)N * 256, 0.0f, (size_t)PADR * 256);
    fill_kernel<<<ceil_div((long long)PADR * 256, TB), TB>>>(bufB + (size_t)N * 256, 0.0f, (size_t)PADR * 256);
    fill_kernel<<<ceil_div((long long)PADR * 128, TB), TB>>>(bufA + (size_t)N * 128, 0.0f, (size_t)PADR * 128);
    fill_kernel<<<ceil_div((long long)PADR * 128, TB), TB>>>(bufB + (size_t)N * 128, 0.0f, (size_t)PADR * 128);

    for (int t = 0; t < 2; t++) {
        const int* rows = ei[t];
        const int* cols = ei[t] + E;

        // ---- build CSR by destination: deg -> dinv, offsets, fill (reused by 4 layers)
        zero_int_kernel<<<ceil_div(N, TB), TB>>>(deg, N);
        hist_kernel<<<ceil_div(E, TB), TB>>>(cols, deg, E);
        dinv_kernel<<<ceil_div(N, TB), TB>>>(deg, dinv, N);
        scan_partial_kernel<<<NB_SCAN, 256>>>(deg, bsum, N);
        scan_top_kernel<<<1, 256>>>(bsum, NB_SCAN);
        scan_apply_kernel<<<NB_SCAN, 256>>>(deg, bsum, off, cur, N);
        csr_fill_kernel<<<ceil_div(E, TB), TB>>>(rows, cols, dinv, cur, ridx, wsrc, E);

        // ---- layer 1: aggregate x (128) -> bufA, GEMM+bias+relu -> bufB[*,256]
        agg_csr_kernel<128, false><<<AGG_BLK, 256>>>(x[t], bufA, off, ridx, wsrc, dinv,
                                                     (const int*)0, (const float*)0, (float*)0, 0, N);
        tc_gemm<true, true><<<dim3(256 / 64, MPAD / 128), 256>>>(bufA, Wc1, bc1, bufB, MPAD, 128, 256, 256, 0);

        // ---- layer 2: aggregate bufB (256) -> bufA, GEMM -> bufB
        agg_csr_kernel<256, false><<<AGG_BLK, 256>>>(bufB, bufA, off, ridx, wsrc, dinv,
                                                     (const int*)0, (const float*)0, (float*)0, 0, N);
        tc_gemm<true, true><<<dim3(256 / 64, MPAD / 128), 256>>>(bufA, Wc2, bc2, bufB, MPAD, 256, 256, 256, 0);

        // ---- layer 3
        agg_csr_kernel<256, false><<<AGG_BLK, 256>>>(bufB, bufA, off, ridx, wsrc, dinv,
                                                     (const int*)0, (const float*)0, (float*)0, 0, N);
        tc_gemm<true, true><<<dim3(256 / 64, MPAD / 128), 256>>>(bufA, Wc3, bc3, bufB, MPAD, 256, 256, 256, 0);

        // ---- layer 4: GEMM (no bias/relu) -> bufA[*,128]; agg fused with pool
        tc_gemm<false, false><<<dim3(128 / 64, MPAD / 128), 256>>>(bufB, Wc4, (const float*)0, bufA, MPAD, 256, 128, 128, 0);
        fill_kernel<<<ceil_div(G, TB), TB>>>(cnt, 0.0f, (size_t)G);
        count_kernel<<<ceil_div(N, TB), TB>>>(batch[t], cnt, N);
        agg_csr_kernel<128, true><<<AGG_BLK, 256>>>(bufA, (float*)0, off, ridx, wsrc, dinv,
                                                    batch[t], bc4, cbuf, t * H2, N);
        pool_div_kernel<<<ceil_div(G * H2, TB), TB>>>(cbuf, cnt, t * H2);

        // ---- notes MLP into c[:, 256 + t*128 : ...]
        tc_gemm<true, true><<<dim3(256 / 64, G / 128), 256>>>(notes[t], Wn1, bn1b, t1, G, 128, 256, 256, 0);
        tc_gemm<true, true><<<dim3(128 / 64, G / 128), 256>>>(t1, Wn2, bn2b, cbuf, G, 256, 128, CCOLS, 256 + t * H2);
    }

    // ---- head: f1 = BN(relu(c @ Wf1 + bf1))
    tc_gemm<true, true><<<dim3(256 / 64, G / 128), 256>>>(cbuf, Wf1, bf1, t1, G, 512, 256, 256, 0);
    bn_stats_kernel<<<256, 256>>>(t1, 256, mu, istd);
    bn_apply_kernel<<<ceil_div((long long)G * 256, TB), TB>>>(t1, mu, istd, g1, be1, 256, G * 256);

    // f2 = BN(relu(f1 @ Wf2 + bf2))
    tc_gemm<true, true><<<dim3(128 / 64, G / 128), 256>>>(t1, Wf2, bf2, t2, G, 256, 128, 128, 0);
    bn_stats_kernel<<<128, 256>>>(t2, 128, mu, istd);
    bn_apply_kernel<<<ceil_div((long long)G * 128, TB), TB>>>(t2, mu, istd, g2, be2, 128, G * 128);

    // out = f2 @ Wf3 + bf3
    tc_gemm<false, true><<<dim3(128 / 64, G / 128), 256>>>(t2, Wf3, bf3, (float*)d_out, G, 128, 128, 128, 0);
}

// round 5
// speedup vs baseline: 4.0056x; 1.2733x over previous
#include <cuda_runtime.h>
#include <cuda_fp16.h>
#include <math.h>
#include <stdint.h>

#define N_NODES 200000
#define N_PAD   200064          // padded to multiple of 128 for TC GEMM
#define N_EDGES 3200000
#define G_GRAPHS 8192
#define HID 256
#define H2 128
#define CCOLS 512
#define EPS 1e-5f
#define SCAN_CHUNK 2048

// ---------------- scratch (device globals; no runtime alloc) ----------------
__device__ __half g_hX[(size_t)N_PAD * 128];
__device__ __half g_hA[(size_t)N_PAD * HID];
__device__ __half g_hB[(size_t)N_PAD * HID];
__device__ float g_dinv[N_NODES];
__device__ int   g_deg[N_NODES];
__device__ int   g_off[N_NODES];
__device__ int   g_cur[N_NODES];
__device__ int   g_bsum[256];
__device__ int   g_ridx[N_EDGES];
__device__ float g_wsrc[N_EDGES];
__device__ float g_cnt[G_GRAPHS];
__device__ float g_c[(size_t)G_GRAPHS * CCOLS];
__device__ float g_t1[(size_t)G_GRAPHS * HID];
__device__ float g_t2[(size_t)G_GRAPHS * H2];
__device__ float g_mu[HID];
__device__ float g_istd[HID];

// vectorized fp32 reduction to global memory (sm_90+)
__device__ __forceinline__ void red_add_v4(float* addr, float4 v) {
    asm volatile("red.global.add.v4.f32 [%0], {%1, %2, %3, %4};"
                 :: "l"(addr), "f"(v.x), "f"(v.y), "f"(v.z), "f"(v.w)
                 : "memory");
}

// ---------------- utility kernels ----------------
__global__ void fill_kernel(float* __restrict__ p, float v, size_t n) {
    size_t i = (size_t)blockIdx.x * blockDim.x + threadIdx.x;
    if (i < n) p[i] = v;
}

__global__ void fillh_kernel(__half* __restrict__ p, size_t n2) {  // n2 = half2 count
    size_t i = (size_t)blockIdx.x * blockDim.x + threadIdx.x;
    if (i < n2) ((__half2*)p)[i] = __floats2half2_rn(0.f, 0.f);
}

__global__ void f2h_kernel(const float* __restrict__ in, __half* __restrict__ out, size_t n2) {
    size_t i = (size_t)blockIdx.x * blockDim.x + threadIdx.x;
    if (i < n2) {
        float2 v = ((const float2*)in)[i];
        ((__half2*)out)[i] = __floats2half2_rn(v.x, v.y);
    }
}

__global__ void zero_int_kernel(int* __restrict__ p, int n) {
    int i = blockIdx.x * blockDim.x + threadIdx.x;
    if (i < n) p[i] = 0;
}

__global__ void hist_kernel(const int* __restrict__ cols, int* __restrict__ deg, int nE) {
    int i = blockIdx.x * blockDim.x + threadIdx.x;
    if (i < nE) atomicAdd(&deg[cols[i]], 1);
}

__global__ void dinv_kernel(const int* __restrict__ deg, float* __restrict__ dinv, int n) {
    int i = blockIdx.x * blockDim.x + threadIdx.x;
    if (i < n) dinv[i] = rsqrtf((float)deg[i] + 1.0f);  // +1 for self loop
}

// ---------------- exclusive scan (3-phase) over g_deg -> g_off, g_cur ----------------
__global__ void scan_partial_kernel(const int* __restrict__ deg, int* __restrict__ bsum, int n) {
    __shared__ int sh[256];
    int t = threadIdx.x;
    int base = blockIdx.x * SCAN_CHUNK + t * 8;
    int s = 0;
#pragma unroll
    for (int k = 0; k < 8; k++)
        if (base + k < n) s += deg[base + k];
    sh[t] = s;
    __syncthreads();
    for (int o = 128; o > 0; o >>= 1) {
        if (t < o) sh[t] += sh[t + o];
        __syncthreads();
    }
    if (t == 0) bsum[blockIdx.x] = sh[0];
}

__global__ void scan_top_kernel(int* __restrict__ bsum, int nb) {
    __shared__ int sh[256];
    int t = threadIdx.x;
    int v = (t < nb) ? bsum[t] : 0;
    sh[t] = v;
    __syncthreads();
    for (int o = 1; o < 256; o <<= 1) {
        int x = (t >= o) ? sh[t - o] : 0;
        __syncthreads();
        sh[t] += x;
        __syncthreads();
    }
    if (t < nb) bsum[t] = sh[t] - v;  // exclusive
}

__global__ void scan_apply_kernel(const int* __restrict__ deg, const int* __restrict__ bsum,
                                  int* __restrict__ off, int* __restrict__ cur, int n) {
    __shared__ int sh[256];
    int t = threadIdx.x;
    int base = blockIdx.x * SCAN_CHUNK + t * 8;
    int loc[8];
    int s = 0;
#pragma unroll
    for (int k = 0; k < 8; k++) {
        loc[k] = (base + k < n) ? deg[base + k] : 0;
        s += loc[k];
    }
    sh[t] = s;
    __syncthreads();
    for (int o = 1; o < 256; o <<= 1) {
        int x = (t >= o) ? sh[t - o] : 0;
        __syncthreads();
        sh[t] += x;
        __syncthreads();
    }
    int run = bsum[blockIdx.x] + sh[t] - s;
#pragma unroll
    for (int k = 0; k < 8; k++) {
        if (base + k < n) {
            off[base + k] = run;
            cur[base + k] = run;
            run += loc[k];
        }
    }
}

__global__ void csr_fill_kernel(const int* __restrict__ rows, const int* __restrict__ cols,
                                const float* __restrict__ dinv, int* __restrict__ cur,
                                int* __restrict__ ridx, float* __restrict__ wsrc, int nE) {
    int e = blockIdx.x * blockDim.x + threadIdx.x;
    if (e >= nE) return;
    int c = cols[e], r = rows[e];
    int p = atomicAdd(&cur[c], 1);
    ridx[p] = r;
    wsrc[p] = dinv[r];
}

// ---------------- CSR gather aggregation on fp16 features ----------------
// out[i,:] = dinv[i] * ( sum_{r in in(i)} dinv[r]*in[r,:] + dinv[i]*in[i,:] )
// one warp per destination node; fp32 accumulation; fp16 in/out.
// POOL (D=128 only): red_add(cbuf[batch[i]*CCOLS+coff], relu(acc + bias)).
template <int D, bool POOL>
__global__ __launch_bounds__(256) void agg_csr_h(
    const __half* __restrict__ in, __half* __restrict__ out,
    const int* __restrict__ off, const int* __restrict__ ridx,
    const float* __restrict__ wsrc, const float* __restrict__ dinv,
    const int* __restrict__ batch, const float* __restrict__ bias,
    float* __restrict__ cbuf, int coff, int n) {
    int node = blockIdx.x * (blockDim.x >> 5) + (threadIdx.x >> 5);
    if (node >= n) return;
    int lane = threadIdx.x & 31;
    int s = off[node];
    int e = (node == n - 1) ? N_EDGES : off[node + 1];
    float dc = dinv[node];

    constexpr int HPL = D / 32;          // halfs per lane (4 or 8)
    float acc[HPL];
    // self term
    {
        const __half2* sp = (const __half2*)(in + (size_t)node * D) + lane * (HPL / 2);
#pragma unroll
        for (int v = 0; v < HPL / 2; v++) {
            float2 f = __half22float2(sp[v]);
            acc[2 * v] = f.x * dc;
            acc[2 * v + 1] = f.y * dc;
        }
    }
    for (int j = s; j < e; j++) {
        int r = ridx[j];
        float w = wsrc[j];
        const __half2* sp = (const __half2*)(in + (size_t)r * D) + lane * (HPL / 2);
        __half2 h[HPL / 2];
#pragma unroll
        for (int v = 0; v < HPL / 2; v++) h[v] = sp[v];
#pragma unroll
        for (int v = 0; v < HPL / 2; v++) {
            float2 f = __half22float2(h[v]);
            acc[2 * v] += f.x * w;
            acc[2 * v + 1] += f.y * w;
        }
    }
#pragma unroll
    for (int v = 0; v < HPL; v++) acc[v] *= dc;

    if (POOL) {
        float4 b = *(const float4*)&bias[lane * 4];
        float4 v0;
        v0.x = fmaxf(acc[0] + b.x, 0.0f);
        v0.y = fmaxf(acc[1] + b.y, 0.0f);
        v0.z = fmaxf(acc[2] + b.z, 0.0f);
        v0.w = fmaxf(acc[3] + b.w, 0.0f);
        red_add_v4(&cbuf[(size_t)batch[node] * CCOLS + coff + lane * 4], v0);
    } else {
        __half2* dst = (__half2*)(out + (size_t)node * D) + lane * (HPL / 2);
#pragma unroll
        for (int v = 0; v < HPL / 2; v++)
            dst[v] = __floats2half2_rn(acc[2 * v], acc[2 * v + 1]);
    }
}

__global__ void count_kernel(const int* __restrict__ batch, float* __restrict__ cnt, int n) {
    int i = blockIdx.x * blockDim.x + threadIdx.x;
    if (i < n) atomicAdd(&cnt[batch[i]], 1.0f);
}

__global__ void pool_div_kernel(float* __restrict__ c, const float* __restrict__ cnt, int coff) {
    int idx = blockIdx.x * blockDim.x + threadIdx.x;
    if (idx >= G_GRAPHS * H2) return;
    int g = idx >> 7, d = idx & 127;
    c[(size_t)g * CCOLS + coff + d] *= 1.0f / fmaxf(cnt[g], 1.0f);
}

// ---------------- tf32 helpers ----------------
__device__ __forceinline__ void tf32_split(float x, uint32_t& h, uint32_t& l) {
    asm("cvt.rna.tf32.f32 %0, %1;" : "=r"(h) : "f"(x));
    float r = x - __uint_as_float(h);
    asm("cvt.rna.tf32.f32 %0, %1;" : "=r"(l) : "f"(r));
}

__device__ __forceinline__ uint32_t tf32_cvt(float x) {  // exact for fp16-derived values
    uint32_t h;
    asm("cvt.rna.tf32.f32 %0, %1;" : "=r"(h) : "f"(x));
    return h;
}

__device__ __forceinline__ void mma_tf32(float* c,
                                         uint32_t a0, uint32_t a1, uint32_t a2, uint32_t a3,
                                         uint32_t b0, uint32_t b1) {
    asm volatile(
        "mma.sync.aligned.m16n8k8.row.col.f32.tf32.tf32.f32 "
        "{%0,%1,%2,%3}, {%4,%5,%6,%7}, {%8,%9}, {%0,%1,%2,%3};"
        : "+f"(c[0]), "+f"(c[1]), "+f"(c[2]), "+f"(c[3])
        : "r"(a0), "r"(a1), "r"(a2), "r"(a3), "r"(b0), "r"(b1));
}

// ---------------- fp32 TC GEMM (3xTF32) for head/notes ----------------
template <bool RELU, bool BIAS>
__global__ __launch_bounds__(256) void tc_gemm(
    const float* __restrict__ A, const float* __restrict__ W,
    const float* __restrict__ bias, float* __restrict__ C,
    int M, int K, int N, int ldc, int coff) {
    __shared__ float As[128][20];
    __shared__ float Bs[16][72];

    int tid = threadIdx.x;
    int bm = blockIdx.y * 128, bn = blockIdx.x * 64;
    int warp = tid >> 5, lane = tid & 31;
    int wm = (warp & 3) * 32, wn = (warp >> 2) * 32;
    int g = lane >> 2, tig = lane & 3;

    float acc[2][4][4] = {};

    for (int k0 = 0; k0 < K; k0 += 16) {
#pragma unroll
        for (int i = 0; i < 2; i++) {
            int idx = tid + i * 256;
            int row = idx >> 2, c4 = (idx & 3) << 2;
            float4 v = *(const float4*)&A[(size_t)(bm + row) * K + k0 + c4];
            As[row][c4 + 0] = v.x; As[row][c4 + 1] = v.y;
            As[row][c4 + 2] = v.z; As[row][c4 + 3] = v.w;
        }
        {
            int row = tid >> 4, c4 = (tid & 15) << 2;
            float4 v = *(const float4*)&W[(size_t)(k0 + row) * N + bn + c4];
            Bs[row][c4 + 0] = v.x; Bs[row][c4 + 1] = v.y;
            Bs[row][c4 + 2] = v.z; Bs[row][c4 + 3] = v.w;
        }
        __syncthreads();

#pragma unroll
        for (int k8 = 0; k8 < 16; k8 += 8) {
            uint32_t ah[2][4], al[2][4], bh[4][2], bl[4][2];
#pragma unroll
            for (int mt = 0; mt < 2; mt++) {
                int m = wm + mt * 16 + g;
                tf32_split(As[m][k8 + tig],         ah[mt][0], al[mt][0]);
                tf32_split(As[m + 8][k8 + tig],     ah[mt][1], al[mt][1]);
                tf32_split(As[m][k8 + tig + 4],     ah[mt][2], al[mt][2]);
                tf32_split(As[m + 8][k8 + tig + 4], ah[mt][3], al[mt][3]);
            }
#pragma unroll
            for (int nt = 0; nt < 4; nt++) {
                int n = wn + nt * 8 + g;
                tf32_split(Bs[k8 + tig][n],     bh[nt][0], bl[nt][0]);
                tf32_split(Bs[k8 + tig + 4][n], bh[nt][1], bl[nt][1]);
            }
#pragma unroll
            for (int mt = 0; mt < 2; mt++)
#pragma unroll
                for (int nt = 0; nt < 4; nt++) {
                    mma_tf32(acc[mt][nt], ah[mt][0], ah[mt][1], ah[mt][2], ah[mt][3],
                             bh[nt][0], bh[nt][1]);
                    mma_tf32(acc[mt][nt], ah[mt][0], ah[mt][1], ah[mt][2], ah[mt][3],
                             bl[nt][0], bl[nt][1]);
                    mma_tf32(acc[mt][nt], al[mt][0], al[mt][1], al[mt][2], al[mt][3],
                             bh[nt][0], bh[nt][1]);
                }
        }
        __syncthreads();
    }

#pragma unroll
    for (int mt = 0; mt < 2; mt++) {
        int row0 = bm + wm + mt * 16 + g;
#pragma unroll
        for (int nt = 0; nt < 4; nt++) {
            int col = bn + wn + nt * 8 + 2 * tig;
            float b0 = 0.f, b1 = 0.f;
            if (BIAS) { b0 = bias[col]; b1 = bias[col + 1]; }
            float v0 = acc[mt][nt][0] + b0;
            float v1 = acc[mt][nt][1] + b1;
            float v2 = acc[mt][nt][2] + b0;
            float v3 = acc[mt][nt][3] + b1;
            if (RELU) {
                v0 = fmaxf(v0, 0.f); v1 = fmaxf(v1, 0.f);
                v2 = fmaxf(v2, 0.f); v3 = fmaxf(v3, 0.f);
            }
            *(float2*)&C[(size_t)row0 * ldc + coff + col] = make_float2(v0, v1);
            *(float2*)&C[(size_t)(row0 + 8) * ldc + coff + col] = make_float2(v2, v3);
        }
    }
}

// ---------------- fp16-A TC GEMM for tower layers ----------------
// A fp16 (exactly representable in tf32 -> no A-split), W fp32 (hi/lo split),
// output fp16 (optionally bias+relu).
template <bool RELU, bool BIAS>
__global__ __launch_bounds__(256) void tc_gemm_h(
    const __half* __restrict__ A, const float* __restrict__ W,
    const float* __restrict__ bias, __half* __restrict__ C,
    int M, int K, int N, int ldc) {
    __shared__ float As[128][20];
    __shared__ float Bs[16][72];

    int tid = threadIdx.x;
    int bm = blockIdx.y * 128, bn = blockIdx.x * 64;
    int warp = tid >> 5, lane = tid & 31;
    int wm = (warp & 3) * 32, wn = (warp >> 2) * 32;
    int g = lane >> 2, tig = lane & 3;

    float acc[2][4][4] = {};

    for (int k0 = 0; k0 < K; k0 += 16) {
        // ---- A tile (128x16 halfs): each thread one uint4 = 8 halfs
        {
            int row = tid >> 1, c8 = (tid & 1) * 8;
            const __half2* ap = (const __half2*)(A + (size_t)(bm + row) * K + k0 + c8);
            __half2 h0 = ap[0], h1 = ap[1], h2 = ap[2], h3 = ap[3];
            float2 f0 = __half22float2(h0), f1 = __half22float2(h1);
            float2 f2 = __half22float2(h2), f3 = __half22float2(h3);
            As[row][c8 + 0] = f0.x; As[row][c8 + 1] = f0.y;
            As[row][c8 + 2] = f1.x; As[row][c8 + 3] = f1.y;
            As[row][c8 + 4] = f2.x; As[row][c8 + 5] = f2.y;
            As[row][c8 + 6] = f3.x; As[row][c8 + 7] = f3.y;
        }
        // ---- W tile (16x64 fp32)
        {
            int row = tid >> 4, c4 = (tid & 15) << 2;
            float4 v = *(const float4*)&W[(size_t)(k0 + row) * N + bn + c4];
            Bs[row][c4 + 0] = v.x; Bs[row][c4 + 1] = v.y;
            Bs[row][c4 + 2] = v.z; Bs[row][c4 + 3] = v.w;
        }
        __syncthreads();

#pragma unroll
        for (int k8 = 0; k8 < 16; k8 += 8) {
            uint32_t ah[2][4], bh[4][2], bl[4][2];
#pragma unroll
            for (int mt = 0; mt < 2; mt++) {
                int m = wm + mt * 16 + g;
                ah[mt][0] = tf32_cvt(As[m][k8 + tig]);
                ah[mt][1] = tf32_cvt(As[m + 8][k8 + tig]);
                ah[mt][2] = tf32_cvt(As[m][k8 + tig + 4]);
                ah[mt][3] = tf32_cvt(As[m + 8][k8 + tig + 4]);
            }
#pragma unroll
            for (int nt = 0; nt < 4; nt++) {
                int n = wn + nt * 8 + g;
                tf32_split(Bs[k8 + tig][n],     bh[nt][0], bl[nt][0]);
                tf32_split(Bs[k8 + tig + 4][n], bh[nt][1], bl[nt][1]);
            }
#pragma unroll
            for (int mt = 0; mt < 2; mt++)
#pragma unroll
                for (int nt = 0; nt < 4; nt++) {
                    mma_tf32(acc[mt][nt], ah[mt][0], ah[mt][1], ah[mt][2], ah[mt][3],
                             bh[nt][0], bh[nt][1]);
                    mma_tf32(acc[mt][nt], ah[mt][0], ah[mt][1], ah[mt][2], ah[mt][3],
                             bl[nt][0], bl[nt][1]);
                }
        }
        __syncthreads();
    }

#pragma unroll
    for (int mt = 0; mt < 2; mt++) {
        int row0 = bm + wm + mt * 16 + g;
#pragma unroll
        for (int nt = 0; nt < 4; nt++) {
            int col = bn + wn + nt * 8 + 2 * tig;
            float b0 = 0.f, b1 = 0.f;
            if (BIAS) { b0 = bias[col]; b1 = bias[col + 1]; }
            float v0 = acc[mt][nt][0] + b0;
            float v1 = acc[mt][nt][1] + b1;
            float v2 = acc[mt][nt][2] + b0;
            float v3 = acc[mt][nt][3] + b1;
            if (RELU) {
                v0 = fmaxf(v0, 0.f); v1 = fmaxf(v1, 0.f);
                v2 = fmaxf(v2, 0.f); v3 = fmaxf(v3, 0.f);
            }
            *(__half2*)&C[(size_t)row0 * ldc + col] = __floats2half2_rn(v0, v1);
            *(__half2*)&C[(size_t)(row0 + 8) * ldc + col] = __floats2half2_rn(v2, v3);
        }
    }
}

// ---------------- batch norm ----------------
__global__ void bn_stats_kernel(const float* __restrict__ X, int C,
                                float* __restrict__ mu, float* __restrict__ istd) {
    int c = blockIdx.x;
    int tid = threadIdx.x;
    float s = 0.f, s2 = 0.f;
    for (int r = tid; r < G_GRAPHS; r += 256) {
        float v = X[(size_t)r * C + c];
        s += v;
        s2 += v * v;
    }
    __shared__ float sh[256], sh2[256];
    sh[tid] = s;
    sh2[tid] = s2;
    __syncthreads();
    for (int o = 128; o > 0; o >>= 1) {
        if (tid < o) {
            sh[tid] += sh[tid + o];
            sh2[tid] += sh2[tid + o];
        }
        __syncthreads();
    }
    if (tid == 0) {
        float m = sh[0] / (float)G_GRAPHS;
        float var = sh2[0] / (float)G_GRAPHS - m * m;
        mu[c] = m;
        istd[c] = rsqrtf(var + EPS);
    }
}

__global__ void bn_apply_kernel(float* __restrict__ X, const float* __restrict__ mu,
                                const float* __restrict__ istd, const float* __restrict__ gamma,
                                const float* __restrict__ beta, int C, int total) {
    int idx = blockIdx.x * blockDim.x + threadIdx.x;
    if (idx >= total) return;
    int c = idx % C;
    X[idx] = (X[idx] - mu[c]) * istd[c] * gamma[c] + beta[c];
}

// ---------------- host launcher ----------------
static inline int ceil_div(long long a, int b) { return (int)((a + b - 1) / b); }

extern "C" void kernel_launch(void* const* d_in, const int* in_sizes, int n_in,
                              void* d_out, int out_size) {
    const float* x[2] = {(const float*)d_in[0], (const float*)d_in[1]};
    const int* ei[2] = {(const int*)d_in[2], (const int*)d_in[3]};
    const int* batch[2] = {(const int*)d_in[4], (const int*)d_in[5]};
    const float* notes[2] = {(const float*)d_in[6], (const float*)d_in[7]};
    const float* Wc1 = (const float*)d_in[8];  const float* bc1 = (const float*)d_in[9];
    const float* Wc2 = (const float*)d_in[10]; const float* bc2 = (const float*)d_in[11];
    const float* Wc3 = (const float*)d_in[12]; const float* bc3 = (const float*)d_in[13];
    const float* Wc4 = (const float*)d_in[14]; const float* bc4 = (const float*)d_in[15];
    const float* Wn1 = (const float*)d_in[16]; const float* bn1b = (const float*)d_in[17];
    const float* Wn2 = (const float*)d_in[18]; const float* bn2b = (const float*)d_in[19];
    const float* Wf1 = (const float*)d_in[20]; const float* bf1 = (const float*)d_in[21];
    const float* g1 = (const float*)d_in[22];  const float* be1 = (const float*)d_in[23];
    const float* Wf2 = (const float*)d_in[24]; const float* bf2 = (const float*)d_in[25];
    const float* g2 = (const float*)d_in[26];  const float* be2 = (const float*)d_in[27];
    const float* Wf3 = (const float*)d_in[28]; const float* bf3 = (const float*)d_in[29];

    __half *hX, *hA, *hB;
    float *dinv, *cnt, *cbuf, *t1, *t2, *mu, *istd, *wsrc;
    int *deg, *off, *cur, *bsum, *ridx;
    cudaGetSymbolAddress((void**)&hX, g_hX);
    cudaGetSymbolAddress((void**)&hA, g_hA);
    cudaGetSymbolAddress((void**)&hB, g_hB);
    cudaGetSymbolAddress((void**)&dinv, g_dinv);
    cudaGetSymbolAddress((void**)&deg, g_deg);
    cudaGetSymbolAddress((void**)&off, g_off);
    cudaGetSymbolAddress((void**)&cur, g_cur);
    cudaGetSymbolAddress((void**)&bsum, g_bsum);
    cudaGetSymbolAddress((void**)&ridx, g_ridx);
    cudaGetSymbolAddress((void**)&wsrc, g_wsrc);
    cudaGetSymbolAddress((void**)&cnt, g_cnt);
    cudaGetSymbolAddress((void**)&cbuf, g_c);
    cudaGetSymbolAddress((void**)&t1, g_t1);
    cudaGetSymbolAddress((void**)&t2, g_t2);
    cudaGetSymbolAddress((void**)&mu, g_mu);
    cudaGetSymbolAddress((void**)&istd, g_istd);

    const int TB = 256;
    const int N = N_NODES, E = N_EDGES, G = G_GRAPHS;
    const int MPAD = N_PAD;
    const int PADR = N_PAD - N_NODES;
    const int NB_SCAN = ceil_div(N, SCAN_CHUNK);   // 98
    const int AGG_BLK = ceil_div(N, 8);

    // zero concat buffer (pooling accumulates into it)
    fill_kernel<<<ceil_div((long long)G * CCOLS, TB), TB>>>(cbuf, 0.0f, (size_t)G * CCOLS);
    // zero pad rows of half buffers in both stride senses (deterministic GEMM pads)
    fillh_kernel<<<ceil_div((long long)PADR * 64, TB), TB>>>(hX + (size_t)N * 128, (size_t)PADR * 64);
    fillh_kernel<<<ceil_div((long long)PADR * 64, TB), TB>>>(hA + (size_t)N * 128, (size_t)PADR * 64);
    fillh_kernel<<<ceil_div((long long)PADR * 128, TB), TB>>>(hA + (size_t)N * 256, (size_t)PADR * 128);
    fillh_kernel<<<ceil_div((long long)PADR * 64, TB), TB>>>(hB + (size_t)N * 128, (size_t)PADR * 64);
    fillh_kernel<<<ceil_div((long long)PADR * 128, TB), TB>>>(hB + (size_t)N * 256, (size_t)PADR * 128);

    for (int t = 0; t < 2; t++) {
        const int* rows = ei[t];
        const int* cols = ei[t] + E;

        // ---- build CSR by destination (reused by all 4 layers)
        zero_int_kernel<<<ceil_div(N, TB), TB>>>(deg, N);
        hist_kernel<<<ceil_div(E, TB), TB>>>(cols, deg, E);
        dinv_kernel<<<ceil_div(N, TB), TB>>>(deg, dinv, N);
        scan_partial_kernel<<<NB_SCAN, 256>>>(deg, bsum, N);
        scan_top_kernel<<<1, 256>>>(bsum, NB_SCAN);
        scan_apply_kernel<<<NB_SCAN, 256>>>(deg, bsum, off, cur, N);
        csr_fill_kernel<<<ceil_div(E, TB), TB>>>(rows, cols, dinv, cur, ridx, wsrc, E);

        // ---- x -> fp16
        f2h_kernel<<<ceil_div((long long)N * 64, TB), TB>>>(x[t], hX, (size_t)N * 64);

        // ---- layer 1: agg hX (128) -> hA; GEMM+bias+relu -> hB[*,256]
        agg_csr_h<128, false><<<AGG_BLK, 256>>>(hX, hA, off, ridx, wsrc, dinv,
                                                (const int*)0, (const float*)0, (float*)0, 0, N);
        tc_gemm_h<true, true><<<dim3(256 / 64, MPAD / 128), 256>>>(hA, Wc1, bc1, hB, MPAD, 128, 256, 256);

        // ---- layer 2
        agg_csr_h<256, false><<<AGG_BLK, 256>>>(hB, hA, off, ridx, wsrc, dinv,
                                                (const int*)0, (const float*)0, (float*)0, 0, N);
        tc_gemm_h<true, true><<<dim3(256 / 64, MPAD / 128), 256>>>(hA, Wc2, bc2, hB, MPAD, 256, 256, 256);

        // ---- layer 3
        agg_csr_h<256, false><<<AGG_BLK, 256>>>(hB, hA, off, ridx, wsrc, dinv,
                                                (const int*)0, (const float*)0, (float*)0, 0, N);
        tc_gemm_h<true, true><<<dim3(256 / 64, MPAD / 128), 256>>>(hA, Wc3, bc3, hB, MPAD, 256, 256, 256);

        // ---- layer 4: GEMM first (no bias/relu) -> hA[*,128]; agg fused with pool
        tc_gemm_h<false, false><<<dim3(128 / 64, MPAD / 128), 256>>>(hB, Wc4, (const float*)0, hA, MPAD, 256, 128, 128);
        fill_kernel<<<ceil_div(G, TB), TB>>>(cnt, 0.0f, (size_t)G);
        count_kernel<<<ceil_div(N, TB), TB>>>(batch[t], cnt, N);
        agg_csr_h<128, true><<<AGG_BLK, 256>>>(hA, (__half*)0, off, ridx, wsrc, dinv,
                                               batch[t], bc4, cbuf, t * H2, N);
        pool_div_kernel<<<ceil_div(G * H2, TB), TB>>>(cbuf, cnt, t * H2);

        // ---- notes MLP into c[:, 256 + t*128 : ...] (fp32 path)
        tc_gemm<true, true><<<dim3(256 / 64, G / 128), 256>>>(notes[t], Wn1, bn1b, t1, G, 128, 256, 256, 0);
        tc_gemm<true, true><<<dim3(128 / 64, G / 128), 256>>>(t1, Wn2, bn2b, cbuf, G, 256, 128, CCOLS, 256 + t * H2);
    }

    // ---- head: f1 = BN(relu(c @ Wf1 + bf1))
    tc_gemm<true, true><<<dim3(256 / 64, G / 128), 256>>>(cbuf, Wf1, bf1, t1, G, 512, 256, 256, 0);
    bn_stats_kernel<<<256, 256>>>(t1, 256, mu, istd);
    bn_apply_kernel<<<ceil_div((long long)G * 256, TB), TB>>>(t1, mu, istd, g1, be1, 256, G * 256);

    // f2 = BN(relu(f1 @ Wf2 + bf2))
    tc_gemm<true, true><<<dim3(128 / 64, G / 128), 256>>>(t1, Wf2, bf2, t2, G, 256, 128, 128, 0);
    bn_stats_kernel<<<128, 256>>>(t2, 128, mu, istd);
    bn_apply_kernel<<<ceil_div((long long)G * 128, TB), TB>>>(t2, mu, istd, g2, be2, 128, G * 128);

    // out = f2 @ Wf3 + bf3
    tc_gemm<false, true><<<dim3(128 / 64, G / 128), 256>>>(t2, Wf3, bf3, (float*)d_out, G, 128, 128, 128, 0);
}

// round 6
// speedup vs baseline: 5.9443x; 1.4840x over previous
#include <cuda_runtime.h>
#include <cuda_fp16.h>
#include <math.h>
#include <stdint.h>

#define N_NODES 200000
#define N_PAD   200064          // padded to multiple of 128 for TC GEMM
#define N_EDGES 3200000
#define G_GRAPHS 8192
#define HID 256
#define H2 128
#define CCOLS 512
#define EPS 1e-5f
#define SCAN_CHUNK 2048

// ---------------- scratch (device globals; no runtime alloc) ----------------
__device__ __half g_hX[(size_t)N_PAD * 128];
__device__ __half g_hA[(size_t)N_PAD * HID];
__device__ __half g_hB[(size_t)N_PAD * HID];
__device__ __half g_w1h[128 * 256];
__device__ __half g_w2h[256 * 256];
__device__ __half g_w3h[256 * 256];
__device__ __half g_w4h[256 * 128];
__device__ float g_dinv[N_NODES];
__device__ int   g_deg[N_NODES];
__device__ int   g_off[N_NODES];
__device__ int   g_cur[N_NODES];
__device__ int   g_bsum[256];
__device__ int2  g_edge[N_EDGES];     // (src_row, dinv[src] bits)
__device__ float g_cnt[G_GRAPHS];
__device__ float g_c[(size_t)G_GRAPHS * CCOLS];
__device__ float g_t1[(size_t)G_GRAPHS * HID];
__device__ float g_t2[(size_t)G_GRAPHS * H2];
__device__ float g_mu[HID];
__device__ float g_istd[HID];

// vectorized fp32 reduction to global memory (sm_90+)
__device__ __forceinline__ void red_add_v4(float* addr, float4 v) {
    asm volatile("red.global.add.v4.f32 [%0], {%1, %2, %3, %4};"
                 :: "l"(addr), "f"(v.x), "f"(v.y), "f"(v.z), "f"(v.w)
                 : "memory");
}

// ---------------- utility kernels ----------------
__global__ void fill_kernel(float* __restrict__ p, float v, size_t n) {
    size_t i = (size_t)blockIdx.x * blockDim.x + threadIdx.x;
    if (i < n) p[i] = v;
}

__global__ void fillh_kernel(__half* __restrict__ p, size_t n2) {  // n2 = half2 count
    size_t i = (size_t)blockIdx.x * blockDim.x + threadIdx.x;
    if (i < n2) ((__half2*)p)[i] = __floats2half2_rn(0.f, 0.f);
}

__global__ void f2h_kernel(const float* __restrict__ in, __half* __restrict__ out, size_t n2) {
    size_t i = (size_t)blockIdx.x * blockDim.x + threadIdx.x;
    if (i < n2) {
        float2 v = ((const float2*)in)[i];
        ((__half2*)out)[i] = __floats2half2_rn(v.x, v.y);
    }
}

__global__ void zero_int_kernel(int* __restrict__ p, int n) {
    int i = blockIdx.x * blockDim.x + threadIdx.x;
    if (i < n) p[i] = 0;
}

__global__ void hist_kernel(const int* __restrict__ cols, int* __restrict__ deg, int nE) {
    int i = blockIdx.x * blockDim.x + threadIdx.x;
    if (i < nE) atomicAdd(&deg[cols[i]], 1);
}

__global__ void dinv_kernel(const int* __restrict__ deg, float* __restrict__ dinv, int n) {
    int i = blockIdx.x * blockDim.x + threadIdx.x;
    if (i < n) dinv[i] = rsqrtf((float)deg[i] + 1.0f);  // +1 for self loop
}

// ---------------- exclusive scan (3-phase) over g_deg -> g_off, g_cur ----------------
__global__ void scan_partial_kernel(const int* __restrict__ deg, int* __restrict__ bsum, int n) {
    __shared__ int sh[256];
    int t = threadIdx.x;
    int base = blockIdx.x * SCAN_CHUNK + t * 8;
    int s = 0;
#pragma unroll
    for (int k = 0; k < 8; k++)
        if (base + k < n) s += deg[base + k];
    sh[t] = s;
    __syncthreads();
    for (int o = 128; o > 0; o >>= 1) {
        if (t < o) sh[t] += sh[t + o];
        __syncthreads();
    }
    if (t == 0) bsum[blockIdx.x] = sh[0];
}

__global__ void scan_top_kernel(int* __restrict__ bsum, int nb) {
    __shared__ int sh[256];
    int t = threadIdx.x;
    int v = (t < nb) ? bsum[t] : 0;
    sh[t] = v;
    __syncthreads();
    for (int o = 1; o < 256; o <<= 1) {
        int x = (t >= o) ? sh[t - o] : 0;
        __syncthreads();
        sh[t] += x;
        __syncthreads();
    }
    if (t < nb) bsum[t] = sh[t] - v;  // exclusive
}

__global__ void scan_apply_kernel(const int* __restrict__ deg, const int* __restrict__ bsum,
                                  int* __restrict__ off, int* __restrict__ cur, int n) {
    __shared__ int sh[256];
    int t = threadIdx.x;
    int base = blockIdx.x * SCAN_CHUNK + t * 8;
    int loc[8];
    int s = 0;
#pragma unroll
    for (int k = 0; k < 8; k++) {
        loc[k] = (base + k < n) ? deg[base + k] : 0;
        s += loc[k];
    }
    sh[t] = s;
    __syncthreads();
    for (int o = 1; o < 256; o <<= 1) {
        int x = (t >= o) ? sh[t - o] : 0;
        __syncthreads();
        sh[t] += x;
        __syncthreads();
    }
    int run = bsum[blockIdx.x] + sh[t] - s;
#pragma unroll
    for (int k = 0; k < 8; k++) {
        if (base + k < n) {
            off[base + k] = run;
            cur[base + k] = run;
            run += loc[k];
        }
    }
}

__global__ void csr_fill_kernel(const int* __restrict__ rows, const int* __restrict__ cols,
                                const float* __restrict__ dinv, int* __restrict__ cur,
                                int2* __restrict__ edges, int nE) {
    int e = blockIdx.x * blockDim.x + threadIdx.x;
    if (e >= nE) return;
    int c = cols[e], r = rows[e];
    int p = atomicAdd(&cur[c], 1);
    edges[p] = make_int2(r, __float_as_int(dinv[r]));
}

// ---------------- CSR gather aggregation on fp16 features ----------------
// out[i,:] = dinv[i] * ( sum_{r in in(i)} dinv[r]*in[r,:] + dinv[i]*in[i,:] )
// one warp per destination node; fp32 accumulation; vectorized row gathers.
template <int D, bool POOL>
__global__ __launch_bounds__(256) void agg_csr_h(
    const __half* __restrict__ in, __half* __restrict__ out,
    const int* __restrict__ off, const int2* __restrict__ edges,
    const float* __restrict__ dinv,
    const int* __restrict__ batch, const float* __restrict__ bias,
    float* __restrict__ cbuf, int coff, int n) {
    int node = blockIdx.x * (blockDim.x >> 5) + (threadIdx.x >> 5);
    if (node >= n) return;
    int lane = threadIdx.x & 31;
    int s = off[node];
    int e = (node == n - 1) ? N_EDGES : off[node + 1];
    float dc = dinv[node];

    constexpr int HPL = D / 32;          // halfs per lane (4 or 8)
    float acc[HPL];

    if (D == 256) {
        // 16B per lane
        uint4 u = *((const uint4*)(in + (size_t)node * D) + lane);
        const __half2* hp = (const __half2*)&u;
#pragma unroll
        for (int v = 0; v < 4; v++) {
            float2 f = __half22float2(hp[v]);
            acc[2 * v] = f.x * dc;
            acc[2 * v + 1] = f.y * dc;
        }
        for (int j = s; j < e; j++) {
            int2 ed = edges[j];
            float w = __int_as_float(ed.y);
            uint4 x = *((const uint4*)(in + (size_t)ed.x * D) + lane);
            const __half2* xp = (const __half2*)&x;
#pragma unroll
            for (int v = 0; v < 4; v++) {
                float2 f = __half22float2(xp[v]);
                acc[2 * v] += f.x * w;
                acc[2 * v + 1] += f.y * w;
            }
        }
    } else {
        // D==128: 8B per lane
        uint2 u = *((const uint2*)(in + (size_t)node * D) + lane);
        const __half2* hp = (const __half2*)&u;
#pragma unroll
        for (int v = 0; v < 2; v++) {
            float2 f = __half22float2(hp[v]);
            acc[2 * v] = f.x * dc;
            acc[2 * v + 1] = f.y * dc;
        }
        for (int j = s; j < e; j++) {
            int2 ed = edges[j];
            float w = __int_as_float(ed.y);
            uint2 x = *((const uint2*)(in + (size_t)ed.x * D) + lane);
            const __half2* xp = (const __half2*)&x;
#pragma unroll
            for (int v = 0; v < 2; v++) {
                float2 f = __half22float2(xp[v]);
                acc[2 * v] += f.x * w;
                acc[2 * v + 1] += f.y * w;
            }
        }
    }
#pragma unroll
    for (int v = 0; v < HPL; v++) acc[v] *= dc;

    if (POOL) {
        // D==128: lane owns cols 4*lane..4*lane+3? No: uint2 layout = halfs [4*lane..4*lane+3]
        float4 b = *(const float4*)&bias[lane * 4];
        float4 v0;
        v0.x = fmaxf(acc[0] + b.x, 0.0f);
        v0.y = fmaxf(acc[1] + b.y, 0.0f);
        v0.z = fmaxf(acc[2] + b.z, 0.0f);
        v0.w = fmaxf(acc[3] + b.w, 0.0f);
        red_add_v4(&cbuf[(size_t)batch[node] * CCOLS + coff + lane * 4], v0);
    } else if (D == 256) {
        uint4 o;
        __half2* op = (__half2*)&o;
#pragma unroll
        for (int v = 0; v < 4; v++) op[v] = __floats2half2_rn(acc[2 * v], acc[2 * v + 1]);
        *((uint4*)(out + (size_t)node * D) + lane) = o;
    } else {
        uint2 o;
        __half2* op = (__half2*)&o;
#pragma unroll
        for (int v = 0; v < 2; v++) op[v] = __floats2half2_rn(acc[2 * v], acc[2 * v + 1]);
        *((uint2*)(out + (size_t)node * D) + lane) = o;
    }
}

__global__ void count_kernel(const int* __restrict__ batch, float* __restrict__ cnt, int n) {
    int i = blockIdx.x * blockDim.x + threadIdx.x;
    if (i < n) atomicAdd(&cnt[batch[i]], 1.0f);
}

__global__ void pool_div_kernel(float* __restrict__ c, const float* __restrict__ cnt, int coff) {
    int idx = blockIdx.x * blockDim.x + threadIdx.x;
    if (idx >= G_GRAPHS * H2) return;
    int g = idx >> 7, d = idx & 127;
    c[(size_t)g * CCOLS + coff + d] *= 1.0f / fmaxf(cnt[g], 1.0f);
}

// ---------------- fp16 HMMA GEMM for tower layers ----------------
// C[M,N] = (relu)(A[M,K] @ W[K,N] (+bias)); A,W,C fp16, fp32 accumulate.
// BM=128, BN=64, BK=32; 256 threads = 8 warps (4 M x 2 N), 32x32 warp tile.
#define APAD 40   // halfs per As row (32 + 8): conflict-free (20m+tig mod 32)
template <bool RELU, bool BIAS>
__global__ __launch_bounds__(256) void hgemm(
    const __half* __restrict__ A, const __half* __restrict__ W,
    const float* __restrict__ bias, __half* __restrict__ C,
    int M, int K, int N, int ldc) {
    __shared__ __half As[128][APAD];
    __shared__ __half Bst[64][APAD];   // transposed W tile: [n][k]

    int tid = threadIdx.x;
    int bm = blockIdx.y * 128, bn = blockIdx.x * 64;
    int warp = tid >> 5, lane = tid & 31;
    int wm = (warp & 3) * 32, wn = (warp >> 2) * 32;
    int g = lane >> 2, tig = lane & 3;

    float acc[2][4][4] = {};

    for (int k0 = 0; k0 < K; k0 += 32) {
        // ---- A tile 128x32 halfs: 2 x uint4 (8 halfs) per thread
#pragma unroll
        for (int it = 0; it < 2; it++) {
            int idx = tid + it * 256;
            int row = idx >> 2, c8 = (idx & 3) << 3;
            uint4 v = *(const uint4*)(A + (size_t)(bm + row) * K + k0 + c8);
            *(uint4*)&As[row][c8] = v;
        }
        // ---- W tile 32x64 halfs, store transposed: thread loads 8 halfs of row k
        {
            int k = tid >> 3, n0 = (tid & 7) << 3;
            uint4 v = *(const uint4*)(W + (size_t)(k0 + k) * N + bn + n0);
            const __half* hv = (const __half*)&v;
#pragma unroll
            for (int i = 0; i < 8; i++) Bst[n0 + i][k] = hv[i];
        }
        __syncthreads();

#pragma unroll
        for (int k16 = 0; k16 < 32; k16 += 16) {
            uint32_t a[2][4], b[4][2];
#pragma unroll
            for (int mt = 0; mt < 2; mt++) {
                int m = wm + mt * 16 + g;
                a[mt][0] = *(const uint32_t*)&As[m][k16 + 2 * tig];
                a[mt][1] = *(const uint32_t*)&As[m + 8][k16 + 2 * tig];
                a[mt][2] = *(const uint32_t*)&As[m][k16 + 2 * tig + 8];
                a[mt][3] = *(const uint32_t*)&As[m + 8][k16 + 2 * tig + 8];
            }
#pragma unroll
            for (int nt = 0; nt < 4; nt++) {
                int n = wn + nt * 8 + g;
                b[nt][0] = *(const uint32_t*)&Bst[n][k16 + 2 * tig];
                b[nt][1] = *(const uint32_t*)&Bst[n][k16 + 2 * tig + 8];
            }
#pragma unroll
            for (int mt = 0; mt < 2; mt++)
#pragma unroll
                for (int nt = 0; nt < 4; nt++) {
                    asm volatile(
                        "mma.sync.aligned.m16n8k16.row.col.f32.f16.f16.f32 "
                        "{%0,%1,%2,%3}, {%4,%5,%6,%7}, {%8,%9}, {%0,%1,%2,%3};"
                        : "+f"(acc[mt][nt][0]), "+f"(acc[mt][nt][1]),
                          "+f"(acc[mt][nt][2]), "+f"(acc[mt][nt][3])
                        : "r"(a[mt][0]), "r"(a[mt][1]), "r"(a[mt][2]), "r"(a[mt][3]),
                          "r"(b[nt][0]), "r"(b[nt][1]));
                }
        }
        __syncthreads();
    }

#pragma unroll
    for (int mt = 0; mt < 2; mt++) {
        int row0 = bm + wm + mt * 16 + g;
#pragma unroll
        for (int nt = 0; nt < 4; nt++) {
            int col = bn + wn + nt * 8 + 2 * tig;
            float b0 = 0.f, b1 = 0.f;
            if (BIAS) { b0 = bias[col]; b1 = bias[col + 1]; }
            float v0 = acc[mt][nt][0] + b0;
            float v1 = acc[mt][nt][1] + b1;
            float v2 = acc[mt][nt][2] + b0;
            float v3 = acc[mt][nt][3] + b1;
            if (RELU) {
                v0 = fmaxf(v0, 0.f); v1 = fmaxf(v1, 0.f);
                v2 = fmaxf(v2, 0.f); v3 = fmaxf(v3, 0.f);
            }
            *(__half2*)&C[(size_t)row0 * ldc + col] = __floats2half2_rn(v0, v1);
            *(__half2*)&C[(size_t)(row0 + 8) * ldc + col] = __floats2half2_rn(v2, v3);
        }
    }
}

// ---------------- tf32 helpers (fp32 GEMM for notes/head) ----------------
__device__ __forceinline__ void tf32_split(float x, uint32_t& h, uint32_t& l) {
    asm("cvt.rna.tf32.f32 %0, %1;" : "=r"(h) : "f"(x));
    float r = x - __uint_as_float(h);
    asm("cvt.rna.tf32.f32 %0, %1;" : "=r"(l) : "f"(r));
}

__device__ __forceinline__ void mma_tf32(float* c,
                                         uint32_t a0, uint32_t a1, uint32_t a2, uint32_t a3,
                                         uint32_t b0, uint32_t b1) {
    asm volatile(
        "mma.sync.aligned.m16n8k8.row.col.f32.tf32.tf32.f32 "
        "{%0,%1,%2,%3}, {%4,%5,%6,%7}, {%8,%9}, {%0,%1,%2,%3};"
        : "+f"(c[0]), "+f"(c[1]), "+f"(c[2]), "+f"(c[3])
        : "r"(a0), "r"(a1), "r"(a2), "r"(a3), "r"(b0), "r"(b1));
}

template <bool RELU, bool BIAS>
__global__ __launch_bounds__(256) void tc_gemm(
    const float* __restrict__ A, const float* __restrict__ W,
    const float* __restrict__ bias, float* __restrict__ C,
    int M, int K, int N, int ldc, int coff) {
    __shared__ float As[128][20];
    __shared__ float Bs[16][72];

    int tid = threadIdx.x;
    int bm = blockIdx.y * 128, bn = blockIdx.x * 64;
    int warp = tid >> 5, lane = tid & 31;
    int wm = (warp & 3) * 32, wn = (warp >> 2) * 32;
    int g = lane >> 2, tig = lane & 3;

    float acc[2][4][4] = {};

    for (int k0 = 0; k0 < K; k0 += 16) {
#pragma unroll
        for (int i = 0; i < 2; i++) {
            int idx = tid + i * 256;
            int row = idx >> 2, c4 = (idx & 3) << 2;
            float4 v = *(const float4*)&A[(size_t)(bm + row) * K + k0 + c4];
            As[row][c4 + 0] = v.x; As[row][c4 + 1] = v.y;
            As[row][c4 + 2] = v.z; As[row][c4 + 3] = v.w;
        }
        {
            int row = tid >> 4, c4 = (tid & 15) << 2;
            float4 v = *(const float4*)&W[(size_t)(k0 + row) * N + bn + c4];
            Bs[row][c4 + 0] = v.x; Bs[row][c4 + 1] = v.y;
            Bs[row][c4 + 2] = v.z; Bs[row][c4 + 3] = v.w;
        }
        __syncthreads();

#pragma unroll
        for (int k8 = 0; k8 < 16; k8 += 8) {
            uint32_t ah[2][4], al[2][4], bh[4][2], bl[4][2];
#pragma unroll
            for (int mt = 0; mt < 2; mt++) {
                int m = wm + mt * 16 + g;
                tf32_split(As[m][k8 + tig],         ah[mt][0], al[mt][0]);
                tf32_split(As[m + 8][k8 + tig],     ah[mt][1], al[mt][1]);
                tf32_split(As[m][k8 + tig + 4],     ah[mt][2], al[mt][2]);
                tf32_split(As[m + 8][k8 + tig + 4], ah[mt][3], al[mt][3]);
            }
#pragma unroll
            for (int nt = 0; nt < 4; nt++) {
                int n = wn + nt * 8 + g;
                tf32_split(Bs[k8 + tig][n],     bh[nt][0], bl[nt][0]);
                tf32_split(Bs[k8 + tig + 4][n], bh[nt][1], bl[nt][1]);
            }
#pragma unroll
            for (int mt = 0; mt < 2; mt++)
#pragma unroll
                for (int nt = 0; nt < 4; nt++) {
                    mma_tf32(acc[mt][nt], ah[mt][0], ah[mt][1], ah[mt][2], ah[mt][3],
                             bh[nt][0], bh[nt][1]);
                    mma_tf32(acc[mt][nt], ah[mt][0], ah[mt][1], ah[mt][2], ah[mt][3],
                             bl[nt][0], bl[nt][1]);
                    mma_tf32(acc[mt][nt], al[mt][0], al[mt][1], al[mt][2], al[mt][3],
                             bh[nt][0], bh[nt][1]);
                }
        }
        __syncthreads();
    }

#pragma unroll
    for (int mt = 0; mt < 2; mt++) {
        int row0 = bm + wm + mt * 16 + g;
#pragma unroll
        for (int nt = 0; nt < 4; nt++) {
            int col = bn + wn + nt * 8 + 2 * tig;
            float b0 = 0.f, b1 = 0.f;
            if (BIAS) { b0 = bias[col]; b1 = bias[col + 1]; }
            float v0 = acc[mt][nt][0] + b0;
            float v1 = acc[mt][nt][1] + b1;
            float v2 = acc[mt][nt][2] + b0;
            float v3 = acc[mt][nt][3] + b1;
            if (RELU) {
                v0 = fmaxf(v0, 0.f); v1 = fmaxf(v1, 0.f);
                v2 = fmaxf(v2, 0.f); v3 = fmaxf(v3, 0.f);
            }
            *(float2*)&C[(size_t)row0 * ldc + coff + col] = make_float2(v0, v1);
            *(float2*)&C[(size_t)(row0 + 8) * ldc + coff + col] = make_float2(v2, v3);
        }
    }
}

// ---------------- batch norm ----------------
__global__ void bn_stats_kernel(const float* __restrict__ X, int C,
                                float* __restrict__ mu, float* __restrict__ istd) {
    int c = blockIdx.x;
    int tid = threadIdx.x;
    float s = 0.f, s2 = 0.f;
    for (int r = tid; r < G_GRAPHS; r += 256) {
        float v = X[(size_t)r * C + c];
        s += v;
        s2 += v * v;
    }
    __shared__ float sh[256], sh2[256];
    sh[tid] = s;
    sh2[tid] = s2;
    __syncthreads();
    for (int o = 128; o > 0; o >>= 1) {
        if (tid < o) {
            sh[tid] += sh[tid + o];
            sh2[tid] += sh2[tid + o];
        }
        __syncthreads();
    }
    if (tid == 0) {
        float m = sh[0] / (float)G_GRAPHS;
        float var = sh2[0] / (float)G_GRAPHS - m * m;
        mu[c] = m;
        istd[c] = rsqrtf(var + EPS);
    }
}

__global__ void bn_apply_kernel(float* __restrict__ X, const float* __restrict__ mu,
                                const float* __restrict__ istd, const float* __restrict__ gamma,
                                const float* __restrict__ beta, int C, int total) {
    int idx = blockIdx.x * blockDim.x + threadIdx.x;
    if (idx >= total) return;
    int c = idx % C;
    X[idx] = (X[idx] - mu[c]) * istd[c] * gamma[c] + beta[c];
}

// ---------------- host launcher ----------------
static inline int ceil_div(long long a, int b) { return (int)((a + b - 1) / b); }

extern "C" void kernel_launch(void* const* d_in, const int* in_sizes, int n_in,
                              void* d_out, int out_size) {
    const float* x[2] = {(const float*)d_in[0], (const float*)d_in[1]};
    const int* ei[2] = {(const int*)d_in[2], (const int*)d_in[3]};
    const int* batch[2] = {(const int*)d_in[4], (const int*)d_in[5]};
    const float* notes[2] = {(const float*)d_in[6], (const float*)d_in[7]};
    const float* Wc1 = (const float*)d_in[8];  const float* bc1 = (const float*)d_in[9];
    const float* Wc2 = (const float*)d_in[10]; const float* bc2 = (const float*)d_in[11];
    const float* Wc3 = (const float*)d_in[12]; const float* bc3 = (const float*)d_in[13];
    const float* Wc4 = (const float*)d_in[14]; const float* bc4 = (const float*)d_in[15];
    const float* Wn1 = (const float*)d_in[16]; const float* bn1b = (const float*)d_in[17];
    const float* Wn2 = (const float*)d_in[18]; const float* bn2b = (const float*)d_in[19];
    const float* Wf1 = (const float*)d_in[20]; const float* bf1 = (const float*)d_in[21];
    const float* g1 = (const float*)d_in[22];  const float* be1 = (const float*)d_in[23];
    const float* Wf2 = (const float*)d_in[24]; const float* bf2 = (const float*)d_in[25];
    const float* g2 = (const float*)d_in[26];  const float* be2 = (const float*)d_in[27];
    const float* Wf3 = (const float*)d_in[28]; const float* bf3 = (const float*)d_in[29];

    __half *hX, *hA, *hB, *w1h, *w2h, *w3h, *w4h;
    float *dinv, *cnt, *cbuf, *t1, *t2, *mu, *istd;
    int *deg, *off, *cur, *bsum;
    int2* edges;
    cudaGetSymbolAddress((void**)&hX, g_hX);
    cudaGetSymbolAddress((void**)&hA, g_hA);
    cudaGetSymbolAddress((void**)&hB, g_hB);
    cudaGetSymbolAddress((void**)&w1h, g_w1h);
    cudaGetSymbolAddress((void**)&w2h, g_w2h);
    cudaGetSymbolAddress((void**)&w3h, g_w3h);
    cudaGetSymbolAddress((void**)&w4h, g_w4h);
    cudaGetSymbolAddress((void**)&dinv, g_dinv);
    cudaGetSymbolAddress((void**)&deg, g_deg);
    cudaGetSymbolAddress((void**)&off, g_off);
    cudaGetSymbolAddress((void**)&cur, g_cur);
    cudaGetSymbolAddress((void**)&bsum, g_bsum);
    cudaGetSymbolAddress((void**)&edges, g_edge);
    cudaGetSymbolAddress((void**)&cnt, g_cnt);
    cudaGetSymbolAddress((void**)&cbuf, g_c);
    cudaGetSymbolAddress((void**)&t1, g_t1);
    cudaGetSymbolAddress((void**)&t2, g_t2);
    cudaGetSymbolAddress((void**)&mu, g_mu);
    cudaGetSymbolAddress((void**)&istd, g_istd);

    const int TB = 256;
    const int N = N_NODES, E = N_EDGES, G = G_GRAPHS;
    const int MPAD = N_PAD;
    const int PADR = N_PAD - N_NODES;
    const int NB_SCAN = ceil_div(N, SCAN_CHUNK);   // 98
    const int AGG_BLK = ceil_div(N, 8);

    // zero concat buffer (pooling accumulates into it)
    fill_kernel<<<ceil_div((long long)G * CCOLS, TB), TB>>>(cbuf, 0.0f, (size_t)G * CCOLS);
    // zero pad rows of half buffers in both stride senses (deterministic GEMM pads)
    fillh_kernel<<<ceil_div((long long)PADR * 64, TB), TB>>>(hX + (size_t)N * 128, (size_t)PADR * 64);
    fillh_kernel<<<ceil_div((long long)PADR * 64, TB), TB>>>(hA + (size_t)N * 128, (size_t)PADR * 64);
    fillh_kernel<<<ceil_div((long long)PADR * 128, TB), TB>>>(hA + (size_t)N * 256, (size_t)PADR * 128);
    fillh_kernel<<<ceil_div((long long)PADR * 64, TB), TB>>>(hB + (size_t)N * 128, (size_t)PADR * 64);
    fillh_kernel<<<ceil_div((long long)PADR * 128, TB), TB>>>(hB + (size_t)N * 256, (size_t)PADR * 128);

    // weights -> fp16 (once per launch)
    f2h_kernel<<<ceil_div(128 * 256 / 2, TB), TB>>>(Wc1, w1h, 128 * 256 / 2);
    f2h_kernel<<<ceil_div(256 * 256 / 2, TB), TB>>>(Wc2, w2h, 256 * 256 / 2);
    f2h_kernel<<<ceil_div(256 * 256 / 2, TB), TB>>>(Wc3, w3h, 256 * 256 / 2);
    f2h_kernel<<<ceil_div(256 * 128 / 2, TB), TB>>>(Wc4, w4h, 256 * 128 / 2);

    for (int t = 0; t < 2; t++) {
        const int* rows = ei[t];
        const int* cols = ei[t] + E;

        // ---- build CSR by destination (reused by all 4 layers)
        zero_int_kernel<<<ceil_div(N, TB), TB>>>(deg, N);
        hist_kernel<<<ceil_div(E, TB), TB>>>(cols, deg, E);
        dinv_kernel<<<ceil_div(N, TB), TB>>>(deg, dinv, N);
        scan_partial_kernel<<<NB_SCAN, 256>>>(deg, bsum, N);
        scan_top_kernel<<<1, 256>>>(bsum, NB_SCAN);
        scan_apply_kernel<<<NB_SCAN, 256>>>(deg, bsum, off, cur, N);
        csr_fill_kernel<<<ceil_div(E, TB), TB>>>(rows, cols, dinv, cur, edges, E);

        // ---- x -> fp16
        f2h_kernel<<<ceil_div((long long)N * 64, TB), TB>>>(x[t], hX, (size_t)N * 64);

        // ---- layer 1: agg hX (128) -> hA; GEMM+bias+relu -> hB[*,256]
        agg_csr_h<128, false><<<AGG_BLK, 256>>>(hX, hA, off, edges, dinv,
                                                (const int*)0, (const float*)0, (float*)0, 0, N);
        hgemm<true, true><<<dim3(256 / 64, MPAD / 128), 256>>>(hA, w1h, bc1, hB, MPAD, 128, 256, 256);

        // ---- layer 2
        agg_csr_h<256, false><<<AGG_BLK, 256>>>(hB, hA, off, edges, dinv,
                                                (const int*)0, (const float*)0, (float*)0, 0, N);
        hgemm<true, true><<<dim3(256 / 64, MPAD / 128), 256>>>(hA, w2h, bc2, hB, MPAD, 256, 256, 256);

        // ---- layer 3
        agg_csr_h<256, false><<<AGG_BLK, 256>>>(hB, hA, off, edges, dinv,
                                                (const int*)0, (const float*)0, (float*)0, 0, N);
        hgemm<true, true><<<dim3(256 / 64, MPAD / 128), 256>>>(hA, w3h, bc3, hB, MPAD, 256, 256, 256);

        // ---- layer 4: GEMM first (no bias/relu) -> hA[*,128]; agg fused with pool
        hgemm<false, false><<<dim3(128 / 64, MPAD / 128), 256>>>(hB, w4h, (const float*)0, hA, MPAD, 256, 128, 128);
        fill_kernel<<<ceil_div(G, TB), TB>>>(cnt, 0.0f, (size_t)G);
        count_kernel<<<ceil_div(N, TB), TB>>>(batch[t], cnt, N);
        agg_csr_h<128, true><<<AGG_BLK, 256>>>(hA, (__half*)0, off, edges, dinv,
                                               batch[t], bc4, cbuf, t * H2, N);
        pool_div_kernel<<<ceil_div(G * H2, TB), TB>>>(cbuf, cnt, t * H2);

        // ---- notes MLP into c[:, 256 + t*128 : ...] (fp32 path)
        tc_gemm<true, true><<<dim3(256 / 64, G / 128), 256>>>(notes[t], Wn1, bn1b, t1, G, 128, 256, 256, 0);
        tc_gemm<true, true><<<dim3(128 / 64, G / 128), 256>>>(t1, Wn2, bn2b, cbuf, G, 256, 128, CCOLS, 256 + t * H2);
    }

    // ---- head: f1 = BN(relu(c @ Wf1 + bf1))
    tc_gemm<true, true><<<dim3(256 / 64, G / 128), 256>>>(cbuf, Wf1, bf1, t1, G, 512, 256, 256, 0);
    bn_stats_kernel<<<256, 256>>>(t1, 256, mu, istd);
    bn_apply_kernel<<<ceil_div((long long)G * 256, TB), TB>>>(t1, mu, istd, g1, be1, 256, G * 256);

    // f2 = BN(relu(f1 @ Wf2 + bf2))
    tc_gemm<true, true><<<dim3(128 / 64, G / 128), 256>>>(t1, Wf2, bf2, t2, G, 256, 128, 128, 0);
    bn_stats_kernel<<<128, 256>>>(t2, 128, mu, istd);
    bn_apply_kernel<<<ceil_div((long long)G * 128, TB), TB>>>(t2, mu, istd, g2, be2, 128, G * 128);

    // out = f2 @ Wf3 + bf3
    tc_gemm<false, true><<<dim3(128 / 64, G / 128), 256>>>(t2, Wf3, bf3, (float*)d_out, G, 128, 128, 128, 0);
}